// round 14
// baseline (speedup 1.0000x reference)
#include <cuda_runtime.h>
#include <cuda_fp16.h>
#include <cstdint>

#define BB 4
#define NT 2048
#define DD 512
#define HH 8
#define DHH 64
#define INNER 512
#define QKVC 1536
#define NJT 32            // 2048/64 j-tiles
#define L2E 1.44269504f
#define SCALE_L2E (0.125f * 1.44269504f)

// Scratch (device globals — no cudaMalloc allowed)
static __device__ __half g_xhi[(size_t)BB * NT * DD];
static __device__ __half g_xlo[(size_t)BB * NT * DD];
static __device__ __half g_wqh[(size_t)QKVC * DD];   // [n][k]
static __device__ __half g_wql[(size_t)QKVC * DD];
static __device__ __half g_woh[(size_t)DD * DD];     // [n][k]
static __device__ __half g_wol[(size_t)DD * DD];
static __device__ __half g_qkv16[(size_t)BB * NT * QKVC];    // fp16 qkv
static __device__ __half g_v16t[(size_t)BB * HH * DHH * NT]; // [b,h,d,n]
static __device__ float  g_bias32[(size_t)BB * HH * NT * NT];// bias*log2e fp32
static __device__ __half g_ohi[(size_t)BB * NT * INNER];
static __device__ __half g_olo[(size_t)BB * NT * INNER];

// ---------------------------------------------------------------------------
// helpers
// ---------------------------------------------------------------------------
__device__ __forceinline__ uint32_t smaddr(const void* p) {
    uint32_t a;
    asm("{.reg .u64 t; cvta.to.shared.u64 t, %1; cvt.u32.u64 %0, t;}"
        : "=r"(a) : "l"(p));
    return a;
}

__device__ __forceinline__ uint32_t pack2h(float lo, float hi) {
    uint32_t d;
    asm("cvt.rn.f16x2.f32 %0, %1, %2;" : "=r"(d) : "f"(hi), "f"(lo));
    return d;
}

__device__ __forceinline__ float ex2f(float x) {
    float y;
    asm("ex2.approx.f32 %0, %1;" : "=f"(y) : "f"(x));
    return y;
}

__device__ __forceinline__ void mma_f16(float c[4], uint32_t a0, uint32_t a1,
                                        uint32_t a2, uint32_t a3,
                                        uint32_t b0, uint32_t b1) {
    asm volatile(
        "mma.sync.aligned.m16n8k16.row.col.f32.f16.f16.f32 "
        "{%0,%1,%2,%3}, {%4,%5,%6,%7}, {%8,%9}, {%0,%1,%2,%3};"
        : "+f"(c[0]), "+f"(c[1]), "+f"(c[2]), "+f"(c[3])
        : "r"(a0), "r"(a1), "r"(a2), "r"(a3), "r"(b0), "r"(b1));
}

__device__ __forceinline__ void bulk_cp(uint32_t dst, const void* src,
                                        uint32_t bytes, uint32_t mbar) {
    asm volatile(
        "cp.async.bulk.shared::cta.global.mbarrier::complete_tx::bytes "
        "[%0], [%1], %2, [%3];"
        :: "r"(dst), "l"(src), "r"(bytes), "r"(mbar) : "memory");
}

__device__ __forceinline__ void mbar_expect(uint32_t mbar, uint32_t bytes) {
    asm volatile("mbarrier.arrive.expect_tx.shared.b64 _, [%0], %1;"
                 :: "r"(mbar), "r"(bytes) : "memory");
}

__device__ __forceinline__ void mbar_wait(uint32_t mbar, uint32_t parity) {
    uint32_t done;
    do {
        asm volatile(
            "{.reg .pred p; "
            "mbarrier.try_wait.parity.acquire.cta.shared::cta.b64 p, [%1], %2, 0x989680; "
            "selp.b32 %0,1,0,p;}"
            : "=r"(done) : "r"(mbar), "r"(parity) : "memory");
    } while (!done);
}

// ---------------------------------------------------------------------------
// split conversion kernels
// ---------------------------------------------------------------------------
__global__ __launch_bounds__(256) void cvt_x_kernel(
    const float* __restrict__ x, __half* __restrict__ xhi,
    __half* __restrict__ xlo)
{
    const size_t i = ((size_t)blockIdx.x * 256 + threadIdx.x) * 4;
    const float4 v = *(const float4*)(x + i);
    const __half2 h0 = __float22half2_rn(make_float2(v.x, v.y));
    const __half2 h1 = __float22half2_rn(make_float2(v.z, v.w));
    const float2 f0 = __half22float2(h0);
    const float2 f1 = __half22float2(h1);
    const __half2 l0 = __float22half2_rn(make_float2(v.x - f0.x, v.y - f0.y));
    const __half2 l1 = __float22half2_rn(make_float2(v.z - f1.x, v.w - f1.y));
    *(__half2*)(xhi + i) = h0;
    *(__half2*)(xhi + i + 2) = h1;
    *(__half2*)(xlo + i) = l0;
    *(__half2*)(xlo + i + 2) = l1;
}

// W [K rows][N cols] -> wh/wl [n][k], split
__global__ __launch_bounds__(256) void cvt_w_kernel(
    const float* __restrict__ W, __half* __restrict__ wh,
    __half* __restrict__ wl, int Ncols)
{
    const int idx = blockIdx.x * 256 + threadIdx.x;
    const int n = idx >> 9, k = idx & 511;
    const float v = W[(size_t)k * Ncols + n];
    const __half h = __float2half_rn(v);
    wh[(size_t)n * DD + k] = h;
    wl[(size_t)n * DD + k] = __float2half_rn(v - __half2float(h));
}

// ---------------------------------------------------------------------------
// bias body: bias32[b,h,i,j] = (sum_c rel_w[h,c]*cd[...] + rel_b[h]) * log2e
// Each thread handles 8 consecutive j (2x float4 per plane: MLP 6).
// ---------------------------------------------------------------------------
__device__ __forceinline__ void bias_body(
    int bid, const float* __restrict__ cd, const float* __restrict__ rel_w,
    const float* __restrict__ rel_b, float* __restrict__ bias32)
{
    const int b = bid >> 11;                       // 2048 blocks per batch
    const size_t pos = (size_t)(bid & 2047) * 2048 + (size_t)threadIdx.x * 8;
    const int i = (int)(pos >> 11);
    const int j = (int)(pos & 2047);
    const size_t NN2 = (size_t)NT * NT;
    const size_t ro = (size_t)i * NT + j;
    const float* p0 = cd + (size_t)b * 3 * NN2 + ro;
    const float4 c0a = *(const float4*)(p0);
    const float4 c0b = *(const float4*)(p0 + 4);
    const float4 c1a = *(const float4*)(p0 + NN2);
    const float4 c1b = *(const float4*)(p0 + NN2 + 4);
    const float4 c2a = *(const float4*)(p0 + 2 * NN2);
    const float4 c2b = *(const float4*)(p0 + 2 * NN2 + 4);
#pragma unroll
    for (int h = 0; h < HH; h++) {
        const float w0 = __ldg(rel_w + h * 3 + 0) * L2E;
        const float w1 = __ldg(rel_w + h * 3 + 1) * L2E;
        const float w2 = __ldg(rel_w + h * 3 + 2) * L2E;
        const float rb = __ldg(rel_b + h) * L2E;
        float4 oa, ob;
        oa.x = w0 * c0a.x + w1 * c1a.x + w2 * c2a.x + rb;
        oa.y = w0 * c0a.y + w1 * c1a.y + w2 * c2a.y + rb;
        oa.z = w0 * c0a.z + w1 * c1a.z + w2 * c2a.z + rb;
        oa.w = w0 * c0a.w + w1 * c1a.w + w2 * c2a.w + rb;
        ob.x = w0 * c0b.x + w1 * c1b.x + w2 * c2b.x + rb;
        ob.y = w0 * c0b.y + w1 * c1b.y + w2 * c2b.y + rb;
        ob.z = w0 * c0b.z + w1 * c1b.z + w2 * c2b.z + rb;
        ob.w = w0 * c0b.w + w1 * c1b.w + w2 * c2b.w + rb;
        float* dst = bias32 + ((size_t)(b * HH + h) * NT + i) * NT + j;
        *(float4*)(dst) = oa;
        *(float4*)(dst + 4) = ob;
    }
}

// ---------------------------------------------------------------------------
// Split-fp16 GEMM body (R10-proven): C = (Ahi+Alo)@(Bhi+Blo)^T via 3 mma.
// Tile 128x64, K-chunk 64, 256 thr.
// dyn smem: AH 18432 @0, AL @18432, BH 9216 @36864, BL @46080 (55296 B)
// ---------------------------------------------------------------------------
template <bool OUT16>
__device__ __forceinline__ void hgemm3_body(
    const __half* __restrict__ Ahi, const __half* __restrict__ Alo,
    const __half* __restrict__ Bhi, const __half* __restrict__ Blo,
    const float* __restrict__ bias, void* __restrict__ Cv, int ldc,
    int bx, int by, char* sh)
{
    __half* AH = (__half*)sh;
    __half* AL = (__half*)(sh + 18432);
    __half* BH = (__half*)(sh + 36864);
    __half* BL = (__half*)(sh + 46080);

    const int tid = threadIdx.x;
    const int lane = tid & 31, w = tid >> 5;
    const int g = lane >> 2, t = lane & 3;
    const int m0 = by << 7, n0 = bx << 6;

    float acc[8][4] = {};

    for (int kc = 0; kc < DD; kc += 64) {
#pragma unroll
        for (int i = 0; i < 4; i++) {
            const int fi = tid + (i << 8);
            const int row = fi >> 3, c8 = (fi & 7) << 3;
            const size_t go = (size_t)(m0 + row) * DD + kc + c8;
            *(float4*)&AH[row * 72 + c8] = *(const float4*)(Ahi + go);
            *(float4*)&AL[row * 72 + c8] = *(const float4*)(Alo + go);
        }
#pragma unroll
        for (int i = 0; i < 2; i++) {
            const int fi = tid + (i << 8);
            const int row = fi >> 3, c8 = (fi & 7) << 3;
            const size_t go = (size_t)(n0 + row) * DD + kc + c8;
            *(float4*)&BH[row * 72 + c8] = *(const float4*)(Bhi + go);
            *(float4*)&BL[row * 72 + c8] = *(const float4*)(Blo + go);
        }
        __syncthreads();
        const uint32_t* ah32 = (const uint32_t*)AH;
        const uint32_t* al32 = (const uint32_t*)AL;
        const uint32_t* bh32 = (const uint32_t*)BH;
        const uint32_t* bl32 = (const uint32_t*)BL;
#pragma unroll
        for (int kk = 0; kk < 4; kk++) {
            const int i0r = (w * 16 + g) * 36 + kk * 8 + t;
            const int i1r = (w * 16 + g + 8) * 36 + kk * 8 + t;
            const uint32_t ah0 = ah32[i0r], ah1 = ah32[i1r];
            const uint32_t ah2 = ah32[i0r + 4], ah3 = ah32[i1r + 4];
            const uint32_t al0 = al32[i0r], al1 = al32[i1r];
            const uint32_t al2 = al32[i0r + 4], al3 = al32[i1r + 4];
#pragma unroll
            for (int nn = 0; nn < 8; nn++) {
                const int bi = (nn * 8 + g) * 36 + kk * 8 + t;
                const uint32_t bh0 = bh32[bi], bh1 = bh32[bi + 4];
                const uint32_t bl0 = bl32[bi], bl1 = bl32[bi + 4];
                mma_f16(acc[nn], ah0, ah1, ah2, ah3, bh0, bh1);
                mma_f16(acc[nn], ah0, ah1, ah2, ah3, bl0, bl1);
                mma_f16(acc[nn], al0, al1, al2, al3, bh0, bh1);
            }
        }
        __syncthreads();
    }

    const int row0 = m0 + w * 16 + g, row1 = row0 + 8;
    if (OUT16) {
        __half* C = (__half*)Cv;
#pragma unroll
        for (int nn = 0; nn < 8; nn++) {
            const int col = n0 + nn * 8 + 2 * t;
            *(uint32_t*)(C + (size_t)row0 * ldc + col) = pack2h(acc[nn][0], acc[nn][1]);
            *(uint32_t*)(C + (size_t)row1 * ldc + col) = pack2h(acc[nn][2], acc[nn][3]);
        }
    } else {
        float* C = (float*)Cv;
#pragma unroll
        for (int nn = 0; nn < 8; nn++) {
            const int col = n0 + nn * 8 + 2 * t;
            const float2 bb = *(const float2*)(bias + col);
            *(float2*)(C + (size_t)row0 * ldc + col) =
                make_float2(acc[nn][0] + bb.x, acc[nn][1] + bb.y);
            *(float2*)(C + (size_t)row1 * ldc + col) =
                make_float2(acc[nn][2] + bb.x, acc[nn][3] + bb.y);
        }
    }
}

// ---------------------------------------------------------------------------
// Fused front-end: 1536 qkv GEMM blocks interleaved with 8192 bias blocks
// (Bresenham stripe g(i)=i*3/19). __launch_bounds__(256,4) caps regs at 64
// so 4 blocks/SM stay resident (smem 4x55296 = 221KB <= 228KB).
// ---------------------------------------------------------------------------
#define GEMM_BLOCKS 1536
#define BIAS_BLOCKS 8192
#define FUSED_TOTAL (GEMM_BLOCKS + BIAS_BLOCKS)

__global__ __launch_bounds__(256, 4) void fused_pre_kernel(
    const float* __restrict__ cd, const float* __restrict__ rel_w,
    const float* __restrict__ rel_b, float* __restrict__ bias32,
    const __half* __restrict__ xhi, const __half* __restrict__ xlo,
    const __half* __restrict__ wqh, const __half* __restrict__ wql,
    __half* __restrict__ qkv16)
{
    extern __shared__ char sh[];
    const int i = blockIdx.x;
    const int gi  = (i * 3) / 19;        // gemm blocks before i
    const int gi1 = ((i + 1) * 3) / 19;
    if (gi1 > gi && gi < GEMM_BLOCKS) {
        hgemm3_body<true>(xhi, xlo, wqh, wql, nullptr, qkv16, QKVC,
                          gi % 24, gi / 24, sh);
    } else {
        const int bid = i - gi1;
        if (bid < BIAS_BLOCKS)
            bias_body(bid, cd, rel_w, rel_b, bias32);
    }
}

// standalone hgemm3 (out-projection)
template <bool OUT16>
__global__ __launch_bounds__(256) void hgemm3_kernel(
    const __half* __restrict__ Ahi, const __half* __restrict__ Alo,
    const __half* __restrict__ Bhi, const __half* __restrict__ Blo,
    const float* __restrict__ bias, void* __restrict__ Cv, int ldc)
{
    extern __shared__ char sh[];
    hgemm3_body<OUT16>(Ahi, Alo, Bhi, Blo, bias, Cv, ldc,
                       blockIdx.x, blockIdx.y, sh);
}

// ---------------------------------------------------------------------------
// V transpose: qkv16 v-part -> v16t [b,h,d,n]
// ---------------------------------------------------------------------------
__global__ __launch_bounds__(256) void vtrans_kernel(
    const __half* __restrict__ qkv16, __half* __restrict__ v16t)
{
    __shared__ __half vs[64 * 72];
    const int tid = threadIdx.x;
    const int h = blockIdx.x & 7;
    const int n0 = (blockIdx.x >> 3) << 6;
    const int b = blockIdx.y;

#pragma unroll
    for (int it = 0; it < 8; it++) {
        const int idx = tid + (it << 8);
        const int j = idx >> 5, d2 = (idx & 31) << 1;
        const __half2 v = *(const __half2*)(qkv16
            + (size_t)(b * NT + n0 + j) * QKVC + 2 * INNER + h * DHH + d2);
        vs[d2 * 72 + j] = __low2half(v);
        vs[(d2 + 1) * 72 + j] = __high2half(v);
    }
    __syncthreads();
#pragma unroll
    for (int it = 0; it < 8; it++) {
        const int idx = tid + (it << 8);
        const int d = idx >> 5, j2 = (idx & 31) << 1;
        *(uint32_t*)(v16t + ((size_t)((b * HH + h) * DHH + d)) * NT + n0 + j2) =
            *(const uint32_t*)&vs[d * 72 + j2];
    }
}

// ---------------------------------------------------------------------------
// Fused flash attention (R12-proven): log2-domain softmax, deferred l-
// reduction, single sync per tile, fp32 bias (premultiplied by log2e).
// smem: KS 2x9216 @0, VT 2x9216 @18432, BS 2x34816 @36864, mbar @106496
// ---------------------------------------------------------------------------
#define KS_B 0
#define KS_SZB 9216
#define VT_B 18432
#define VT_SZB 9216
#define BS_B 36864
#define BS_SZB 34816
#define MB_B 106496
#define ATTN_SMEM_BYTES 106528

__device__ __forceinline__ void copy_kv(int idx, int jn, int buf, int b, int h,
                                        const __half* qkv16, const __half* v16t,
                                        char* smc, uint32_t mbar) {
    mbar_expect(mbar, 128u);
    if (idx < 64) {
        const __half* src = qkv16 + (size_t)(b * NT + jn + idx) * QKVC
                            + INNER + h * DHH;
        bulk_cp(smaddr(smc + KS_B + buf * KS_SZB + idx * 144), src, 128u, mbar);
    } else {
        const int r = idx - 64;
        const __half* src = v16t + ((size_t)((b * HH + h) * DHH + r)) * NT + jn;
        bulk_cp(smaddr(smc + VT_B + buf * VT_SZB + r * 144), src, 128u, mbar);
    }
}

__device__ __forceinline__ void copy_bs(int idx, int jn, int buf, int b, int h,
                                        int i0, const float* bias32,
                                        char* smc, uint32_t mbar) {
    mbar_expect(mbar, 256u);
    const float* src = bias32 + ((size_t)(b * HH + h) * NT + i0 + idx) * NT + jn;
    bulk_cp(smaddr(smc + BS_B + buf * BS_SZB + idx * 272), src, 256u, mbar);
}

__global__ __launch_bounds__(256, 2) void attn_kernel(
    const __half* __restrict__ qkv16, const __half* __restrict__ v16t,
    const float* __restrict__ bias32, __half* __restrict__ ohi,
    __half* __restrict__ olo)
{
    extern __shared__ char smc[];
    const int tid = threadIdx.x;
    const int lane = tid & 31, w = tid >> 5;
    const int g = lane >> 2, t = lane & 3;
    const int h = blockIdx.x & 7;
    const int i0 = (blockIdx.x >> 3) << 7;
    const int b = blockIdx.y;

    const uint32_t mb_kv0 = smaddr(smc + MB_B);
    const uint32_t mb_kv1 = mb_kv0 + 8;
    const uint32_t mb_bs0 = mb_kv0 + 16;
    const uint32_t mb_bs1 = mb_kv0 + 24;

    if (tid == 0) {
        asm volatile("mbarrier.init.shared.b64 [%0], %1;" :: "r"(mb_kv0), "r"(128u) : "memory");
        asm volatile("mbarrier.init.shared.b64 [%0], %1;" :: "r"(mb_kv1), "r"(128u) : "memory");
        asm volatile("mbarrier.init.shared.b64 [%0], %1;" :: "r"(mb_bs0), "r"(128u) : "memory");
        asm volatile("mbarrier.init.shared.b64 [%0], %1;" :: "r"(mb_bs1), "r"(128u) : "memory");
        asm volatile("fence.proxy.async.shared::cta;" ::: "memory");
    }
    __syncthreads();

    if (tid < 128) {
        copy_kv(tid, 0, 0, b, h, qkv16, v16t, smc, mb_kv0);
        copy_kv(tid, 64, 1, b, h, qkv16, v16t, smc, mb_kv1);
    } else {
        copy_bs(tid - 128, 0, 0, b, h, i0, bias32, smc, mb_bs0);
        copy_bs(tid - 128, 64, 1, b, h, i0, bias32, smc, mb_bs1);
    }

    // ---- Q A-fragments from qkv16 ----
    uint32_t qa[4][4];
#pragma unroll
    for (int kk = 0; kk < 4; kk++)
#pragma unroll
        for (int r = 0; r < 4; r++) {
            const int row = i0 + w * 16 + g + ((r & 1) ? 8 : 0);
            const int col = h * DHH + kk * 16 + 2 * t + ((r & 2) ? 8 : 0);
            qa[kk][r] = *(const uint32_t*)(qkv16 + (size_t)(b * NT + row) * QKVC + col);
        }

    float m0 = -1e30f, m1 = -1e30f, l0 = 0.f, l1 = 0.f;
    float o[8][4];
#pragma unroll
    for (int dd = 0; dd < 8; dd++)
        o[dd][0] = o[dd][1] = o[dd][2] = o[dd][3] = 0.f;

    const int rl0 = w * 16 + g, rl1 = rl0 + 8;

    for (int jt = 0; jt < NJT; jt++) {
        const int buf = jt & 1;
        const int par = (jt >> 1) & 1;
        const uint32_t* ksw = (const uint32_t*)(smc + KS_B + buf * KS_SZB);
        const uint32_t* vtw = (const uint32_t*)(smc + VT_B + buf * VT_SZB);
        const float* bsf = (const float*)(smc + BS_B + buf * BS_SZB);

        mbar_wait(buf ? mb_kv1 : mb_kv0, par);

        // ---- S = Q K^T ----
        float s_[8][4];
#pragma unroll
        for (int nn = 0; nn < 8; nn++)
            s_[nn][0] = s_[nn][1] = s_[nn][2] = s_[nn][3] = 0.f;
#pragma unroll
        for (int kk = 0; kk < 4; kk++) {
#pragma unroll
            for (int nn = 0; nn < 8; nn++) {
                const uint32_t b0 = ksw[(nn * 8 + g) * 36 + kk * 8 + t];
                const uint32_t b1 = ksw[(nn * 8 + g) * 36 + kk * 8 + t + 4];
                mma_f16(s_[nn], qa[kk][0], qa[kk][1], qa[kk][2], qa[kk][3], b0, b1);
            }
        }

        mbar_wait(buf ? mb_bs1 : mb_bs0, par);

        // ---- logits in log2 domain: x = S*scale*log2e + bias32 (pre-l2e) ----
        float mx0 = -1e30f, mx1 = -1e30f;
#pragma unroll
        for (int nn = 0; nn < 8; nn++) {
            const int c = nn * 8 + 2 * t;
            const float2 bf0 = *(const float2*)&bsf[rl0 * 68 + c];
            const float2 bf1 = *(const float2*)&bsf[rl1 * 68 + c];
            s_[nn][0] = fmaf(s_[nn][0], SCALE_L2E, bf0.x);
            s_[nn][1] = fmaf(s_[nn][1], SCALE_L2E, bf0.y);
            s_[nn][2] = fmaf(s_[nn][2], SCALE_L2E, bf1.x);
            s_[nn][3] = fmaf(s_[nn][3], SCALE_L2E, bf1.y);
            mx0 = fmaxf(mx0, fmaxf(s_[nn][0], s_[nn][1]));
            mx1 = fmaxf(mx1, fmaxf(s_[nn][2], s_[nn][3]));
        }
#pragma unroll
        for (int off = 1; off <= 2; off <<= 1) {
            mx0 = fmaxf(mx0, __shfl_xor_sync(0xffffffffu, mx0, off));
            mx1 = fmaxf(mx1, __shfl_xor_sync(0xffffffffu, mx1, off));
        }
        const float mn0 = fmaxf(m0, mx0), mn1 = fmaxf(m1, mx1);
        const float fac0 = ex2f(m0 - mn0), fac1 = ex2f(m1 - mn1);
        m0 = mn0; m1 = mn1;
        float rs0 = 0.f, rs1 = 0.f;
#pragma unroll
        for (int nn = 0; nn < 8; nn++) {
            s_[nn][0] = ex2f(s_[nn][0] - mn0);
            s_[nn][1] = ex2f(s_[nn][1] - mn0);
            s_[nn][2] = ex2f(s_[nn][2] - mn1);
            s_[nn][3] = ex2f(s_[nn][3] - mn1);
            rs0 += s_[nn][0] + s_[nn][1];
            rs1 += s_[nn][2] + s_[nn][3];
        }
        // deferred: l stays lane-partial (quad reduction in epilogue)
        l0 = l0 * fac0 + rs0;
        l1 = l1 * fac1 + rs1;
#pragma unroll
        for (int dd = 0; dd < 8; dd++) {
            o[dd][0] *= fac0; o[dd][1] *= fac0;
            o[dd][2] *= fac1; o[dd][3] *= fac1;
        }

        // ---- O += P V (accum frag == A frag, register cvt only) ----
#pragma unroll
        for (int jj = 0; jj < 4; jj++) {
            const uint32_t a0 = pack2h(s_[2 * jj][0], s_[2 * jj][1]);
            const uint32_t a1 = pack2h(s_[2 * jj][2], s_[2 * jj][3]);
            const uint32_t a2 = pack2h(s_[2 * jj + 1][0], s_[2 * jj + 1][1]);
            const uint32_t a3 = pack2h(s_[2 * jj + 1][2], s_[2 * jj + 1][3]);
#pragma unroll
            for (int dd = 0; dd < 8; dd++) {
                const uint32_t b0 = vtw[(dd * 8 + g) * 36 + jj * 8 + t];
                const uint32_t b1 = vtw[(dd * 8 + g) * 36 + jj * 8 + t + 4];
                mma_f16(o[dd], a0, a1, a2, a3, b0, b1);
            }
        }

        __syncthreads();   // KV + bias buffers fully consumed by all warps

        if (jt + 2 < NJT) {
            const int jn = (jt + 2) << 6;
            if (tid < 128)
                copy_kv(tid, jn, buf, b, h, qkv16, v16t, smc,
                        buf ? mb_kv1 : mb_kv0);
            else
                copy_bs(tid - 128, jn, buf, b, h, i0, bias32, smc,
                        buf ? mb_bs1 : mb_bs0);
        }
    }

    // ---- epilogue: quad-reduce l, normalize + split-write O hi/lo ----
    l0 += __shfl_xor_sync(0xffffffffu, l0, 1);
    l0 += __shfl_xor_sync(0xffffffffu, l0, 2);
    l1 += __shfl_xor_sync(0xffffffffu, l1, 1);
    l1 += __shfl_xor_sync(0xffffffffu, l1, 2);
    const float inv0 = 1.0f / l0, inv1 = 1.0f / l1;
    const int row0 = i0 + rl0, row1 = i0 + rl1;
#pragma unroll
    for (int dd = 0; dd < 8; dd++) {
        const int col = h * DHH + dd * 8 + 2 * t;
        const float v00 = o[dd][0] * inv0, v01 = o[dd][1] * inv0;
        const float v10 = o[dd][2] * inv1, v11 = o[dd][3] * inv1;
        const __half2 h0 = __float22half2_rn(make_float2(v00, v01));
        const __half2 h1 = __float22half2_rn(make_float2(v10, v11));
        const float2 hf0 = __half22float2(h0);
        const float2 hf1 = __half22float2(h1);
        const __half2 q0 = __float22half2_rn(make_float2(v00 - hf0.x, v01 - hf0.y));
        const __half2 q1 = __float22half2_rn(make_float2(v10 - hf1.x, v11 - hf1.y));
        *(__half2*)(ohi + (size_t)(b * NT + row0) * INNER + col) = h0;
        *(__half2*)(ohi + (size_t)(b * NT + row1) * INNER + col) = h1;
        *(__half2*)(olo + (size_t)(b * NT + row0) * INNER + col) = q0;
        *(__half2*)(olo + (size_t)(b * NT + row1) * INNER + col) = q1;
    }
}

// ---------------------------------------------------------------------------
extern "C" void kernel_launch(void* const* d_in, const int* in_sizes, int n_in,
                              void* d_out, int out_size)
{
    const float* x     = (const float*)d_in[0];
    const float* cd    = (const float*)d_in[1];
    const float* Wqkv  = (const float*)d_in[2];
    const float* Wout  = (const float*)d_in[3];
    const float* bout  = (const float*)d_in[4];
    const float* rel_w = (const float*)d_in[5];
    const float* rel_b = (const float*)d_in[6];
    float* out = (float*)d_out;

    __half *xhi, *xlo, *wqh, *wql, *woh, *wol, *qkv16, *v16t, *ohi, *olo;
    float *bias32;
    cudaGetSymbolAddress((void**)&xhi, g_xhi);
    cudaGetSymbolAddress((void**)&xlo, g_xlo);
    cudaGetSymbolAddress((void**)&wqh, g_wqh);
    cudaGetSymbolAddress((void**)&wql, g_wql);
    cudaGetSymbolAddress((void**)&woh, g_woh);
    cudaGetSymbolAddress((void**)&wol, g_wol);
    cudaGetSymbolAddress((void**)&qkv16, g_qkv16);
    cudaGetSymbolAddress((void**)&v16t, g_v16t);
    cudaGetSymbolAddress((void**)&bias32, g_bias32);
    cudaGetSymbolAddress((void**)&ohi, g_ohi);
    cudaGetSymbolAddress((void**)&olo, g_olo);

    cudaFuncSetAttribute(attn_kernel, cudaFuncAttributeMaxDynamicSharedMemorySize,
                         ATTN_SMEM_BYTES);
    cudaFuncSetAttribute(fused_pre_kernel,
                         cudaFuncAttributeMaxDynamicSharedMemorySize, 55296);
    cudaFuncSetAttribute(hgemm3_kernel<false>,
                         cudaFuncAttributeMaxDynamicSharedMemorySize, 55296);

    dim3 blk(256);
    // split x and weights to hi/lo fp16
    cvt_x_kernel<<<(BB * NT * DD) / (256 * 4), blk>>>(x, xhi, xlo);
    cvt_w_kernel<<<(QKVC * DD) / 256, blk>>>(Wqkv, wqh, wql, QKVC);
    cvt_w_kernel<<<(DD * DD) / 256, blk>>>(Wout, woh, wol, DD);
    // fused: bias32 (conv1x1 * log2e) blocks interleaved with qkv GEMM blocks
    fused_pre_kernel<<<FUSED_TOTAL, blk, 55296>>>(
        cd, rel_w, rel_b, bias32, xhi, xlo, wqh, wql, qkv16);
    // v transpose per head
    vtrans_kernel<<<dim3(HH * (NT / 64), BB), blk>>>(qkv16, v16t);
    // fused attention -> split O
    attn_kernel<<<dim3(HH * (NT / 128), BB), blk, ATTN_SMEM_BYTES>>>(
        qkv16, v16t, bias32, ohi, olo);
    // out = O @ Wout + bout  (split-fp16, fp32 out)
    hgemm3_kernel<false><<<dim3(DD / 64, (BB * NT) / 128), blk, 55296>>>(
        ohi, olo, woh, wol, bout, out, DD);
}

// round 15
// speedup vs baseline: 1.0032x; 1.0032x over previous
#include <cuda_runtime.h>
#include <cuda_fp16.h>
#include <cstdint>

#define BB 4
#define NT 2048
#define DD 512
#define HH 8
#define DHH 64
#define INNER 512
#define QKVC 1536
#define NJT 32            // 2048/64 j-tiles
#define L2E 1.44269504f
#define SCALE_L2E (0.125f * 1.44269504f)

// Scratch (device globals — no cudaMalloc allowed)
static __device__ __half g_xhi[(size_t)BB * NT * DD];
static __device__ __half g_xlo[(size_t)BB * NT * DD];
static __device__ __half g_wqh[(size_t)QKVC * DD];   // [n][k]
static __device__ __half g_wql[(size_t)QKVC * DD];
static __device__ __half g_woh[(size_t)DD * DD];     // [n][k]
static __device__ __half g_wol[(size_t)DD * DD];
static __device__ __half g_qkv16[(size_t)BB * NT * QKVC];    // fp16 qkv
static __device__ __half g_v16t[(size_t)BB * HH * DHH * NT]; // [b,h,d,n]
static __device__ float  g_bias32[(size_t)BB * HH * NT * NT];// bias*log2e fp32
static __device__ __half g_ohi[(size_t)BB * NT * INNER];
static __device__ __half g_olo[(size_t)BB * NT * INNER];

// ---------------------------------------------------------------------------
// helpers
// ---------------------------------------------------------------------------
__device__ __forceinline__ uint32_t smaddr(const void* p) {
    uint32_t a;
    asm("{.reg .u64 t; cvta.to.shared.u64 t, %1; cvt.u32.u64 %0, t;}"
        : "=r"(a) : "l"(p));
    return a;
}

__device__ __forceinline__ uint32_t pack2h(float lo, float hi) {
    uint32_t d;
    asm("cvt.rn.f16x2.f32 %0, %1, %2;" : "=r"(d) : "f"(hi), "f"(lo));
    return d;
}

__device__ __forceinline__ float ex2f(float x) {
    float y;
    asm("ex2.approx.f32 %0, %1;" : "=f"(y) : "f"(x));
    return y;
}

__device__ __forceinline__ void mma_f16(float c[4], uint32_t a0, uint32_t a1,
                                        uint32_t a2, uint32_t a3,
                                        uint32_t b0, uint32_t b1) {
    asm volatile(
        "mma.sync.aligned.m16n8k16.row.col.f32.f16.f16.f32 "
        "{%0,%1,%2,%3}, {%4,%5,%6,%7}, {%8,%9}, {%0,%1,%2,%3};"
        : "+f"(c[0]), "+f"(c[1]), "+f"(c[2]), "+f"(c[3])
        : "r"(a0), "r"(a1), "r"(a2), "r"(a3), "r"(b0), "r"(b1));
}

__device__ __forceinline__ void bulk_cp(uint32_t dst, const void* src,
                                        uint32_t bytes, uint32_t mbar) {
    asm volatile(
        "cp.async.bulk.shared::cta.global.mbarrier::complete_tx::bytes "
        "[%0], [%1], %2, [%3];"
        :: "r"(dst), "l"(src), "r"(bytes), "r"(mbar) : "memory");
}

__device__ __forceinline__ void mbar_expect(uint32_t mbar, uint32_t bytes) {
    asm volatile("mbarrier.arrive.expect_tx.shared.b64 _, [%0], %1;"
                 :: "r"(mbar), "r"(bytes) : "memory");
}

__device__ __forceinline__ void mbar_wait(uint32_t mbar, uint32_t parity) {
    uint32_t done;
    do {
        asm volatile(
            "{.reg .pred p; "
            "mbarrier.try_wait.parity.acquire.cta.shared::cta.b64 p, [%1], %2, 0x989680; "
            "selp.b32 %0,1,0,p;}"
            : "=r"(done) : "r"(mbar), "r"(parity) : "memory");
    } while (!done);
}

// ---------------------------------------------------------------------------
// split conversion kernels
// ---------------------------------------------------------------------------
__global__ __launch_bounds__(256) void cvt_x_kernel(
    const float* __restrict__ x, __half* __restrict__ xhi,
    __half* __restrict__ xlo)
{
    const size_t i = ((size_t)blockIdx.x * 256 + threadIdx.x) * 4;
    const float4 v = *(const float4*)(x + i);
    const __half2 h0 = __float22half2_rn(make_float2(v.x, v.y));
    const __half2 h1 = __float22half2_rn(make_float2(v.z, v.w));
    const float2 f0 = __half22float2(h0);
    const float2 f1 = __half22float2(h1);
    const __half2 l0 = __float22half2_rn(make_float2(v.x - f0.x, v.y - f0.y));
    const __half2 l1 = __float22half2_rn(make_float2(v.z - f1.x, v.w - f1.y));
    *(__half2*)(xhi + i) = h0;
    *(__half2*)(xhi + i + 2) = h1;
    *(__half2*)(xlo + i) = l0;
    *(__half2*)(xlo + i + 2) = l1;
}

// W [K rows][N cols] -> wh/wl [n][k], split
__global__ __launch_bounds__(256) void cvt_w_kernel(
    const float* __restrict__ W, __half* __restrict__ wh,
    __half* __restrict__ wl, int Ncols)
{
    const int idx = blockIdx.x * 256 + threadIdx.x;
    const int n = idx >> 9, k = idx & 511;
    const float v = W[(size_t)k * Ncols + n];
    const __half h = __float2half_rn(v);
    wh[(size_t)n * DD + k] = h;
    wl[(size_t)n * DD + k] = __float2half_rn(v - __half2float(h));
}

// ---------------------------------------------------------------------------
// bias body: bias32[b,h,i,j] = (sum_c rel_w[h,c]*cd[...] + rel_b[h]) * log2e
// Each thread handles 8 consecutive j (2x float4 per plane: MLP 6).
// ---------------------------------------------------------------------------
__device__ __forceinline__ void bias_body(
    int bid, const float* __restrict__ cd, const float* __restrict__ rel_w,
    const float* __restrict__ rel_b, float* __restrict__ bias32)
{
    const int b = bid >> 11;                       // 2048 blocks per batch
    const size_t pos = (size_t)(bid & 2047) * 2048 + (size_t)threadIdx.x * 8;
    const int i = (int)(pos >> 11);
    const int j = (int)(pos & 2047);
    const size_t NN2 = (size_t)NT * NT;
    const size_t ro = (size_t)i * NT + j;
    const float* p0 = cd + (size_t)b * 3 * NN2 + ro;
    const float4 c0a = *(const float4*)(p0);
    const float4 c0b = *(const float4*)(p0 + 4);
    const float4 c1a = *(const float4*)(p0 + NN2);
    const float4 c1b = *(const float4*)(p0 + NN2 + 4);
    const float4 c2a = *(const float4*)(p0 + 2 * NN2);
    const float4 c2b = *(const float4*)(p0 + 2 * NN2 + 4);
#pragma unroll
    for (int h = 0; h < HH; h++) {
        const float w0 = __ldg(rel_w + h * 3 + 0) * L2E;
        const float w1 = __ldg(rel_w + h * 3 + 1) * L2E;
        const float w2 = __ldg(rel_w + h * 3 + 2) * L2E;
        const float rb = __ldg(rel_b + h) * L2E;
        float4 oa, ob;
        oa.x = w0 * c0a.x + w1 * c1a.x + w2 * c2a.x + rb;
        oa.y = w0 * c0a.y + w1 * c1a.y + w2 * c2a.y + rb;
        oa.z = w0 * c0a.z + w1 * c1a.z + w2 * c2a.z + rb;
        oa.w = w0 * c0a.w + w1 * c1a.w + w2 * c2a.w + rb;
        ob.x = w0 * c0b.x + w1 * c1b.x + w2 * c2b.x + rb;
        ob.y = w0 * c0b.y + w1 * c1b.y + w2 * c2b.y + rb;
        ob.z = w0 * c0b.z + w1 * c1b.z + w2 * c2b.z + rb;
        ob.w = w0 * c0b.w + w1 * c1b.w + w2 * c2b.w + rb;
        float* dst = bias32 + ((size_t)(b * HH + h) * NT + i) * NT + j;
        *(float4*)(dst) = oa;
        *(float4*)(dst + 4) = ob;
    }
}

// ---------------------------------------------------------------------------
// Split-fp16 GEMM body (R10-proven): C = (Ahi+Alo)@(Bhi+Blo)^T via 3 mma.
// Tile 128x64, K-chunk 64, 256 thr.
// dyn smem: AH 18432 @0, AL @18432, BH 9216 @36864, BL @46080 (55296 B)
// ---------------------------------------------------------------------------
template <bool OUT16>
__device__ __forceinline__ void hgemm3_body(
    const __half* __restrict__ Ahi, const __half* __restrict__ Alo,
    const __half* __restrict__ Bhi, const __half* __restrict__ Blo,
    const float* __restrict__ bias, void* __restrict__ Cv, int ldc,
    int bx, int by, char* sh)
{
    __half* AH = (__half*)sh;
    __half* AL = (__half*)(sh + 18432);
    __half* BH = (__half*)(sh + 36864);
    __half* BL = (__half*)(sh + 46080);

    const int tid = threadIdx.x;
    const int lane = tid & 31, w = tid >> 5;
    const int g = lane >> 2, t = lane & 3;
    const int m0 = by << 7, n0 = bx << 6;

    float acc[8][4] = {};

    for (int kc = 0; kc < DD; kc += 64) {
#pragma unroll
        for (int i = 0; i < 4; i++) {
            const int fi = tid + (i << 8);
            const int row = fi >> 3, c8 = (fi & 7) << 3;
            const size_t go = (size_t)(m0 + row) * DD + kc + c8;
            *(float4*)&AH[row * 72 + c8] = *(const float4*)(Ahi + go);
            *(float4*)&AL[row * 72 + c8] = *(const float4*)(Alo + go);
        }
#pragma unroll
        for (int i = 0; i < 2; i++) {
            const int fi = tid + (i << 8);
            const int row = fi >> 3, c8 = (fi & 7) << 3;
            const size_t go = (size_t)(n0 + row) * DD + kc + c8;
            *(float4*)&BH[row * 72 + c8] = *(const float4*)(Bhi + go);
            *(float4*)&BL[row * 72 + c8] = *(const float4*)(Blo + go);
        }
        __syncthreads();
        const uint32_t* ah32 = (const uint32_t*)AH;
        const uint32_t* al32 = (const uint32_t*)AL;
        const uint32_t* bh32 = (const uint32_t*)BH;
        const uint32_t* bl32 = (const uint32_t*)BL;
#pragma unroll
        for (int kk = 0; kk < 4; kk++) {
            const int i0r = (w * 16 + g) * 36 + kk * 8 + t;
            const int i1r = (w * 16 + g + 8) * 36 + kk * 8 + t;
            const uint32_t ah0 = ah32[i0r], ah1 = ah32[i1r];
            const uint32_t ah2 = ah32[i0r + 4], ah3 = ah32[i1r + 4];
            const uint32_t al0 = al32[i0r], al1 = al32[i1r];
            const uint32_t al2 = al32[i0r + 4], al3 = al32[i1r + 4];
#pragma unroll
            for (int nn = 0; nn < 8; nn++) {
                const int bi = (nn * 8 + g) * 36 + kk * 8 + t;
                const uint32_t bh0 = bh32[bi], bh1 = bh32[bi + 4];
                const uint32_t bl0 = bl32[bi], bl1 = bl32[bi + 4];
                mma_f16(acc[nn], ah0, ah1, ah2, ah3, bh0, bh1);
                mma_f16(acc[nn], ah0, ah1, ah2, ah3, bl0, bl1);
                mma_f16(acc[nn], al0, al1, al2, al3, bh0, bh1);
            }
        }
        __syncthreads();
    }

    const int row0 = m0 + w * 16 + g, row1 = row0 + 8;
    if (OUT16) {
        __half* C = (__half*)Cv;
#pragma unroll
        for (int nn = 0; nn < 8; nn++) {
            const int col = n0 + nn * 8 + 2 * t;
            *(uint32_t*)(C + (size_t)row0 * ldc + col) = pack2h(acc[nn][0], acc[nn][1]);
            *(uint32_t*)(C + (size_t)row1 * ldc + col) = pack2h(acc[nn][2], acc[nn][3]);
        }
    } else {
        float* C = (float*)Cv;
#pragma unroll
        for (int nn = 0; nn < 8; nn++) {
            const int col = n0 + nn * 8 + 2 * t;
            const float2 bb = *(const float2*)(bias + col);
            *(float2*)(C + (size_t)row0 * ldc + col) =
                make_float2(acc[nn][0] + bb.x, acc[nn][1] + bb.y);
            *(float2*)(C + (size_t)row1 * ldc + col) =
                make_float2(acc[nn][2] + bb.x, acc[nn][3] + bb.y);
        }
    }
}

// ---------------------------------------------------------------------------
// Fused front-end: 1536 qkv GEMM blocks interleaved with 8192 bias blocks
// (Bresenham stripe g(i)=i*3/19). NO register cap (R14's (256,4) spilled the
// GEMM inner loop); 3 blocks/SM with MLP-6 bias blocks.
// ---------------------------------------------------------------------------
#define GEMM_BLOCKS 1536
#define BIAS_BLOCKS 8192
#define FUSED_TOTAL (GEMM_BLOCKS + BIAS_BLOCKS)

__global__ __launch_bounds__(256) void fused_pre_kernel(
    const float* __restrict__ cd, const float* __restrict__ rel_w,
    const float* __restrict__ rel_b, float* __restrict__ bias32,
    const __half* __restrict__ xhi, const __half* __restrict__ xlo,
    const __half* __restrict__ wqh, const __half* __restrict__ wql,
    __half* __restrict__ qkv16)
{
    extern __shared__ char sh[];
    const int i = blockIdx.x;
    const int gi  = (i * 3) / 19;        // gemm blocks before i
    const int gi1 = ((i + 1) * 3) / 19;
    if (gi1 > gi && gi < GEMM_BLOCKS) {
        hgemm3_body<true>(xhi, xlo, wqh, wql, nullptr, qkv16, QKVC,
                          gi % 24, gi / 24, sh);
    } else {
        const int bid = i - gi1;
        if (bid < BIAS_BLOCKS)
            bias_body(bid, cd, rel_w, rel_b, bias32);
    }
}

// standalone hgemm3 (out-projection)
template <bool OUT16>
__global__ __launch_bounds__(256) void hgemm3_kernel(
    const __half* __restrict__ Ahi, const __half* __restrict__ Alo,
    const __half* __restrict__ Bhi, const __half* __restrict__ Blo,
    const float* __restrict__ bias, void* __restrict__ Cv, int ldc)
{
    extern __shared__ char sh[];
    hgemm3_body<OUT16>(Ahi, Alo, Bhi, Blo, bias, Cv, ldc,
                       blockIdx.x, blockIdx.y, sh);
}

// ---------------------------------------------------------------------------
// V transpose: qkv16 v-part -> v16t [b,h,d,n]
// ---------------------------------------------------------------------------
__global__ __launch_bounds__(256) void vtrans_kernel(
    const __half* __restrict__ qkv16, __half* __restrict__ v16t)
{
    __shared__ __half vs[64 * 72];
    const int tid = threadIdx.x;
    const int h = blockIdx.x & 7;
    const int n0 = (blockIdx.x >> 3) << 6;
    const int b = blockIdx.y;

#pragma unroll
    for (int it = 0; it < 8; it++) {
        const int idx = tid + (it << 8);
        const int j = idx >> 5, d2 = (idx & 31) << 1;
        const __half2 v = *(const __half2*)(qkv16
            + (size_t)(b * NT + n0 + j) * QKVC + 2 * INNER + h * DHH + d2);
        vs[d2 * 72 + j] = __low2half(v);
        vs[(d2 + 1) * 72 + j] = __high2half(v);
    }
    __syncthreads();
#pragma unroll
    for (int it = 0; it < 8; it++) {
        const int idx = tid + (it << 8);
        const int d = idx >> 5, j2 = (idx & 31) << 1;
        *(uint32_t*)(v16t + ((size_t)((b * HH + h) * DHH + d)) * NT + n0 + j2) =
            *(const uint32_t*)&vs[d * 72 + j2];
    }
}

// ---------------------------------------------------------------------------
// Fused flash attention (R12-proven): log2-domain softmax, deferred l-
// reduction, single sync per tile, fp32 bias (premultiplied by log2e).
// smem: KS 2x9216 @0, VT 2x9216 @18432, BS 2x34816 @36864, mbar @106496
// ---------------------------------------------------------------------------
#define KS_B 0
#define KS_SZB 9216
#define VT_B 18432
#define VT_SZB 9216
#define BS_B 36864
#define BS_SZB 34816
#define MB_B 106496
#define ATTN_SMEM_BYTES 106528

__device__ __forceinline__ void copy_kv(int idx, int jn, int buf, int b, int h,
                                        const __half* qkv16, const __half* v16t,
                                        char* smc, uint32_t mbar) {
    mbar_expect(mbar, 128u);
    if (idx < 64) {
        const __half* src = qkv16 + (size_t)(b * NT + jn + idx) * QKVC
                            + INNER + h * DHH;
        bulk_cp(smaddr(smc + KS_B + buf * KS_SZB + idx * 144), src, 128u, mbar);
    } else {
        const int r = idx - 64;
        const __half* src = v16t + ((size_t)((b * HH + h) * DHH + r)) * NT + jn;
        bulk_cp(smaddr(smc + VT_B + buf * VT_SZB + r * 144), src, 128u, mbar);
    }
}

__device__ __forceinline__ void copy_bs(int idx, int jn, int buf, int b, int h,
                                        int i0, const float* bias32,
                                        char* smc, uint32_t mbar) {
    mbar_expect(mbar, 256u);
    const float* src = bias32 + ((size_t)(b * HH + h) * NT + i0 + idx) * NT + jn;
    bulk_cp(smaddr(smc + BS_B + buf * BS_SZB + idx * 272), src, 256u, mbar);
}

__global__ __launch_bounds__(256, 2) void attn_kernel(
    const __half* __restrict__ qkv16, const __half* __restrict__ v16t,
    const float* __restrict__ bias32, __half* __restrict__ ohi,
    __half* __restrict__ olo)
{
    extern __shared__ char smc[];
    const int tid = threadIdx.x;
    const int lane = tid & 31, w = tid >> 5;
    const int g = lane >> 2, t = lane & 3;
    const int h = blockIdx.x & 7;
    const int i0 = (blockIdx.x >> 3) << 7;
    const int b = blockIdx.y;

    const uint32_t mb_kv0 = smaddr(smc + MB_B);
    const uint32_t mb_kv1 = mb_kv0 + 8;
    const uint32_t mb_bs0 = mb_kv0 + 16;
    const uint32_t mb_bs1 = mb_kv0 + 24;

    if (tid == 0) {
        asm volatile("mbarrier.init.shared.b64 [%0], %1;" :: "r"(mb_kv0), "r"(128u) : "memory");
        asm volatile("mbarrier.init.shared.b64 [%0], %1;" :: "r"(mb_kv1), "r"(128u) : "memory");
        asm volatile("mbarrier.init.shared.b64 [%0], %1;" :: "r"(mb_bs0), "r"(128u) : "memory");
        asm volatile("mbarrier.init.shared.b64 [%0], %1;" :: "r"(mb_bs1), "r"(128u) : "memory");
        asm volatile("fence.proxy.async.shared::cta;" ::: "memory");
    }
    __syncthreads();

    if (tid < 128) {
        copy_kv(tid, 0, 0, b, h, qkv16, v16t, smc, mb_kv0);
        copy_kv(tid, 64, 1, b, h, qkv16, v16t, smc, mb_kv1);
    } else {
        copy_bs(tid - 128, 0, 0, b, h, i0, bias32, smc, mb_bs0);
        copy_bs(tid - 128, 64, 1, b, h, i0, bias32, smc, mb_bs1);
    }

    // ---- Q A-fragments from qkv16 ----
    uint32_t qa[4][4];
#pragma unroll
    for (int kk = 0; kk < 4; kk++)
#pragma unroll
        for (int r = 0; r < 4; r++) {
            const int row = i0 + w * 16 + g + ((r & 1) ? 8 : 0);
            const int col = h * DHH + kk * 16 + 2 * t + ((r & 2) ? 8 : 0);
            qa[kk][r] = *(const uint32_t*)(qkv16 + (size_t)(b * NT + row) * QKVC + col);
        }

    float m0 = -1e30f, m1 = -1e30f, l0 = 0.f, l1 = 0.f;
    float o[8][4];
#pragma unroll
    for (int dd = 0; dd < 8; dd++)
        o[dd][0] = o[dd][1] = o[dd][2] = o[dd][3] = 0.f;

    const int rl0 = w * 16 + g, rl1 = rl0 + 8;

    for (int jt = 0; jt < NJT; jt++) {
        const int buf = jt & 1;
        const int par = (jt >> 1) & 1;
        const uint32_t* ksw = (const uint32_t*)(smc + KS_B + buf * KS_SZB);
        const uint32_t* vtw = (const uint32_t*)(smc + VT_B + buf * VT_SZB);
        const float* bsf = (const float*)(smc + BS_B + buf * BS_SZB);

        mbar_wait(buf ? mb_kv1 : mb_kv0, par);

        // ---- S = Q K^T ----
        float s_[8][4];
#pragma unroll
        for (int nn = 0; nn < 8; nn++)
            s_[nn][0] = s_[nn][1] = s_[nn][2] = s_[nn][3] = 0.f;
#pragma unroll
        for (int kk = 0; kk < 4; kk++) {
#pragma unroll
            for (int nn = 0; nn < 8; nn++) {
                const uint32_t b0 = ksw[(nn * 8 + g) * 36 + kk * 8 + t];
                const uint32_t b1 = ksw[(nn * 8 + g) * 36 + kk * 8 + t + 4];
                mma_f16(s_[nn], qa[kk][0], qa[kk][1], qa[kk][2], qa[kk][3], b0, b1);
            }
        }

        mbar_wait(buf ? mb_bs1 : mb_bs0, par);

        // ---- logits in log2 domain: x = S*scale*log2e + bias32 (pre-l2e) ----
        float mx0 = -1e30f, mx1 = -1e30f;
#pragma unroll
        for (int nn = 0; nn < 8; nn++) {
            const int c = nn * 8 + 2 * t;
            const float2 bf0 = *(const float2*)&bsf[rl0 * 68 + c];
            const float2 bf1 = *(const float2*)&bsf[rl1 * 68 + c];
            s_[nn][0] = fmaf(s_[nn][0], SCALE_L2E, bf0.x);
            s_[nn][1] = fmaf(s_[nn][1], SCALE_L2E, bf0.y);
            s_[nn][2] = fmaf(s_[nn][2], SCALE_L2E, bf1.x);
            s_[nn][3] = fmaf(s_[nn][3], SCALE_L2E, bf1.y);
            mx0 = fmaxf(mx0, fmaxf(s_[nn][0], s_[nn][1]));
            mx1 = fmaxf(mx1, fmaxf(s_[nn][2], s_[nn][3]));
        }
#pragma unroll
        for (int off = 1; off <= 2; off <<= 1) {
            mx0 = fmaxf(mx0, __shfl_xor_sync(0xffffffffu, mx0, off));
            mx1 = fmaxf(mx1, __shfl_xor_sync(0xffffffffu, mx1, off));
        }
        const float mn0 = fmaxf(m0, mx0), mn1 = fmaxf(m1, mx1);
        const float fac0 = ex2f(m0 - mn0), fac1 = ex2f(m1 - mn1);
        m0 = mn0; m1 = mn1;
        float rs0 = 0.f, rs1 = 0.f;
#pragma unroll
        for (int nn = 0; nn < 8; nn++) {
            s_[nn][0] = ex2f(s_[nn][0] - mn0);
            s_[nn][1] = ex2f(s_[nn][1] - mn0);
            s_[nn][2] = ex2f(s_[nn][2] - mn1);
            s_[nn][3] = ex2f(s_[nn][3] - mn1);
            rs0 += s_[nn][0] + s_[nn][1];
            rs1 += s_[nn][2] + s_[nn][3];
        }
        // deferred: l stays lane-partial (quad reduction in epilogue)
        l0 = l0 * fac0 + rs0;
        l1 = l1 * fac1 + rs1;
#pragma unroll
        for (int dd = 0; dd < 8; dd++) {
            o[dd][0] *= fac0; o[dd][1] *= fac0;
            o[dd][2] *= fac1; o[dd][3] *= fac1;
        }

        // ---- O += P V (accum frag == A frag, register cvt only) ----
#pragma unroll
        for (int jj = 0; jj < 4; jj++) {
            const uint32_t a0 = pack2h(s_[2 * jj][0], s_[2 * jj][1]);
            const uint32_t a1 = pack2h(s_[2 * jj][2], s_[2 * jj][3]);
            const uint32_t a2 = pack2h(s_[2 * jj + 1][0], s_[2 * jj + 1][1]);
            const uint32_t a3 = pack2h(s_[2 * jj + 1][2], s_[2 * jj + 1][3]);
#pragma unroll
            for (int dd = 0; dd < 8; dd++) {
                const uint32_t b0 = vtw[(dd * 8 + g) * 36 + jj * 8 + t];
                const uint32_t b1 = vtw[(dd * 8 + g) * 36 + jj * 8 + t + 4];
                mma_f16(o[dd], a0, a1, a2, a3, b0, b1);
            }
        }

        __syncthreads();   // KV + bias buffers fully consumed by all warps

        if (jt + 2 < NJT) {
            const int jn = (jt + 2) << 6;
            if (tid < 128)
                copy_kv(tid, jn, buf, b, h, qkv16, v16t, smc,
                        buf ? mb_kv1 : mb_kv0);
            else
                copy_bs(tid - 128, jn, buf, b, h, i0, bias32, smc,
                        buf ? mb_bs1 : mb_bs0);
        }
    }

    // ---- epilogue: quad-reduce l, normalize + split-write O hi/lo ----
    l0 += __shfl_xor_sync(0xffffffffu, l0, 1);
    l0 += __shfl_xor_sync(0xffffffffu, l0, 2);
    l1 += __shfl_xor_sync(0xffffffffu, l1, 1);
    l1 += __shfl_xor_sync(0xffffffffu, l1, 2);
    const float inv0 = 1.0f / l0, inv1 = 1.0f / l1;
    const int row0 = i0 + rl0, row1 = i0 + rl1;
#pragma unroll
    for (int dd = 0; dd < 8; dd++) {
        const int col = h * DHH + dd * 8 + 2 * t;
        const float v00 = o[dd][0] * inv0, v01 = o[dd][1] * inv0;
        const float v10 = o[dd][2] * inv1, v11 = o[dd][3] * inv1;
        const __half2 h0 = __float22half2_rn(make_float2(v00, v01));
        const __half2 h1 = __float22half2_rn(make_float2(v10, v11));
        const float2 hf0 = __half22float2(h0);
        const float2 hf1 = __half22float2(h1);
        const __half2 q0 = __float22half2_rn(make_float2(v00 - hf0.x, v01 - hf0.y));
        const __half2 q1 = __float22half2_rn(make_float2(v10 - hf1.x, v11 - hf1.y));
        *(__half2*)(ohi + (size_t)(b * NT + row0) * INNER + col) = h0;
        *(__half2*)(ohi + (size_t)(b * NT + row1) * INNER + col) = h1;
        *(__half2*)(olo + (size_t)(b * NT + row0) * INNER + col) = q0;
        *(__half2*)(olo + (size_t)(b * NT + row1) * INNER + col) = q1;
    }
}

// ---------------------------------------------------------------------------
extern "C" void kernel_launch(void* const* d_in, const int* in_sizes, int n_in,
                              void* d_out, int out_size)
{
    const float* x     = (const float*)d_in[0];
    const float* cd    = (const float*)d_in[1];
    const float* Wqkv  = (const float*)d_in[2];
    const float* Wout  = (const float*)d_in[3];
    const float* bout  = (const float*)d_in[4];
    const float* rel_w = (const float*)d_in[5];
    const float* rel_b = (const float*)d_in[6];
    float* out = (float*)d_out;

    __half *xhi, *xlo, *wqh, *wql, *woh, *wol, *qkv16, *v16t, *ohi, *olo;
    float *bias32;
    cudaGetSymbolAddress((void**)&xhi, g_xhi);
    cudaGetSymbolAddress((void**)&xlo, g_xlo);
    cudaGetSymbolAddress((void**)&wqh, g_wqh);
    cudaGetSymbolAddress((void**)&wql, g_wql);
    cudaGetSymbolAddress((void**)&woh, g_woh);
    cudaGetSymbolAddress((void**)&wol, g_wol);
    cudaGetSymbolAddress((void**)&qkv16, g_qkv16);
    cudaGetSymbolAddress((void**)&v16t, g_v16t);
    cudaGetSymbolAddress((void**)&bias32, g_bias32);
    cudaGetSymbolAddress((void**)&ohi, g_ohi);
    cudaGetSymbolAddress((void**)&olo, g_olo);

    cudaFuncSetAttribute(attn_kernel, cudaFuncAttributeMaxDynamicSharedMemorySize,
                         ATTN_SMEM_BYTES);
    cudaFuncSetAttribute(fused_pre_kernel,
                         cudaFuncAttributeMaxDynamicSharedMemorySize, 55296);
    cudaFuncSetAttribute(hgemm3_kernel<false>,
                         cudaFuncAttributeMaxDynamicSharedMemorySize, 55296);

    dim3 blk(256);
    // split x and weights to hi/lo fp16
    cvt_x_kernel<<<(BB * NT * DD) / (256 * 4), blk>>>(x, xhi, xlo);
    cvt_w_kernel<<<(QKVC * DD) / 256, blk>>>(Wqkv, wqh, wql, QKVC);
    cvt_w_kernel<<<(DD * DD) / 256, blk>>>(Wout, woh, wol, DD);
    // fused: bias32 (conv1x1 * log2e) blocks interleaved with qkv GEMM blocks
    fused_pre_kernel<<<FUSED_TOTAL, blk, 55296>>>(
        cd, rel_w, rel_b, bias32, xhi, xlo, wqh, wql, qkv16);
    // v transpose per head
    vtrans_kernel<<<dim3(HH * (NT / 64), BB), blk>>>(qkv16, v16t);
    // fused attention -> split O
    attn_kernel<<<dim3(HH * (NT / 128), BB), blk, ATTN_SMEM_BYTES>>>(
        qkv16, v16t, bias32, ohi, olo);
    // out = O @ Wout + bout  (split-fp16, fp32 out)
    hgemm3_kernel<false><<<dim3(DD / 64, (BB * NT) / 128), blk, 55296>>>(
        ohi, olo, woh, wol, bout, out, DD);
}

// round 16
// speedup vs baseline: 1.0664x; 1.0629x over previous
#include <cuda_runtime.h>
#include <cuda_fp16.h>
#include <cstdint>

#define BB 4
#define NT 2048
#define DD 512
#define HH 8
#define DHH 64
#define INNER 512
#define QKVC 1536
#define NJT 32            // 2048/64 j-tiles
#define L2E 1.44269504f
#define SCALE_L2E (0.125f * 1.44269504f)

// Scratch (device globals — no cudaMalloc allowed)
static __device__ __half g_xhi[(size_t)BB * NT * DD];
static __device__ __half g_xlo[(size_t)BB * NT * DD];
static __device__ __half g_wqh[(size_t)QKVC * DD];   // [n][k]
static __device__ __half g_wql[(size_t)QKVC * DD];
static __device__ __half g_woh[(size_t)DD * DD];     // [n][k]
static __device__ __half g_wol[(size_t)DD * DD];
static __device__ __half g_qkv16[(size_t)BB * NT * QKVC];    // fp16 qkv
static __device__ __half g_v16t[(size_t)BB * HH * DHH * NT]; // [b,h,d,n]
static __device__ float  g_bias32[(size_t)BB * HH * NT * NT];// bias*log2e fp32
static __device__ __half g_ohi[(size_t)BB * NT * INNER];
static __device__ __half g_olo[(size_t)BB * NT * INNER];

// ---------------------------------------------------------------------------
// helpers
// ---------------------------------------------------------------------------
__device__ __forceinline__ uint32_t smaddr(const void* p) {
    uint32_t a;
    asm("{.reg .u64 t; cvta.to.shared.u64 t, %1; cvt.u32.u64 %0, t;}"
        : "=r"(a) : "l"(p));
    return a;
}

__device__ __forceinline__ uint32_t pack2h(float lo, float hi) {
    uint32_t d;
    asm("cvt.rn.f16x2.f32 %0, %1, %2;" : "=r"(d) : "f"(hi), "f"(lo));
    return d;
}

__device__ __forceinline__ float ex2f(float x) {
    float y;
    asm("ex2.approx.f32 %0, %1;" : "=f"(y) : "f"(x));
    return y;
}

__device__ __forceinline__ void mma_f16(float c[4], uint32_t a0, uint32_t a1,
                                        uint32_t a2, uint32_t a3,
                                        uint32_t b0, uint32_t b1) {
    asm volatile(
        "mma.sync.aligned.m16n8k16.row.col.f32.f16.f16.f32 "
        "{%0,%1,%2,%3}, {%4,%5,%6,%7}, {%8,%9}, {%0,%1,%2,%3};"
        : "+f"(c[0]), "+f"(c[1]), "+f"(c[2]), "+f"(c[3])
        : "r"(a0), "r"(a1), "r"(a2), "r"(a3), "r"(b0), "r"(b1));
}

__device__ __forceinline__ void ldsm_x4(uint32_t r[4], uint32_t addr) {
    asm volatile(
        "ldmatrix.sync.aligned.m8n8.x4.shared.b16 {%0,%1,%2,%3}, [%4];"
        : "=r"(r[0]), "=r"(r[1]), "=r"(r[2]), "=r"(r[3]) : "r"(addr));
}

__device__ __forceinline__ void bulk_cp(uint32_t dst, const void* src,
                                        uint32_t bytes, uint32_t mbar) {
    asm volatile(
        "cp.async.bulk.shared::cta.global.mbarrier::complete_tx::bytes "
        "[%0], [%1], %2, [%3];"
        :: "r"(dst), "l"(src), "r"(bytes), "r"(mbar) : "memory");
}

__device__ __forceinline__ void mbar_expect(uint32_t mbar, uint32_t bytes) {
    asm volatile("mbarrier.arrive.expect_tx.shared.b64 _, [%0], %1;"
                 :: "r"(mbar), "r"(bytes) : "memory");
}

__device__ __forceinline__ void mbar_wait(uint32_t mbar, uint32_t parity) {
    uint32_t done;
    do {
        asm volatile(
            "{.reg .pred p; "
            "mbarrier.try_wait.parity.acquire.cta.shared::cta.b64 p, [%1], %2, 0x989680; "
            "selp.b32 %0,1,0,p;}"
            : "=r"(done) : "r"(mbar), "r"(parity) : "memory");
    } while (!done);
}

// ---------------------------------------------------------------------------
// split conversion kernels
// ---------------------------------------------------------------------------
__global__ __launch_bounds__(256) void cvt_x_kernel(
    const float* __restrict__ x, __half* __restrict__ xhi,
    __half* __restrict__ xlo)
{
    const size_t i = ((size_t)blockIdx.x * 256 + threadIdx.x) * 4;
    const float4 v = *(const float4*)(x + i);
    const __half2 h0 = __float22half2_rn(make_float2(v.x, v.y));
    const __half2 h1 = __float22half2_rn(make_float2(v.z, v.w));
    const float2 f0 = __half22float2(h0);
    const float2 f1 = __half22float2(h1);
    const __half2 l0 = __float22half2_rn(make_float2(v.x - f0.x, v.y - f0.y));
    const __half2 l1 = __float22half2_rn(make_float2(v.z - f1.x, v.w - f1.y));
    *(__half2*)(xhi + i) = h0;
    *(__half2*)(xhi + i + 2) = h1;
    *(__half2*)(xlo + i) = l0;
    *(__half2*)(xlo + i + 2) = l1;
}

// W [K rows][N cols] -> wh/wl [n][k], split
__global__ __launch_bounds__(256) void cvt_w_kernel(
    const float* __restrict__ W, __half* __restrict__ wh,
    __half* __restrict__ wl, int Ncols)
{
    const int idx = blockIdx.x * 256 + threadIdx.x;
    const int n = idx >> 9, k = idx & 511;
    const float v = W[(size_t)k * Ncols + n];
    const __half h = __float2half_rn(v);
    wh[(size_t)n * DD + k] = h;
    wl[(size_t)n * DD + k] = __float2half_rn(v - __half2float(h));
}

// ---------------------------------------------------------------------------
// bias body (R13-proven, MLP-3): 4 j-elements per thread
// ---------------------------------------------------------------------------
__device__ __forceinline__ void bias_body(
    int bid, const float* __restrict__ cd, const float* __restrict__ rel_w,
    const float* __restrict__ rel_b, float* __restrict__ bias32)
{
    const int b = bid >> 12;                       // 4096 blocks per batch
    const size_t pos = (size_t)(bid & 4095) * 256 + threadIdx.x;
    const int i = (int)(pos >> 9);
    const int j = (int)(pos & 511) << 2;
    const size_t NN2 = (size_t)NT * NT;
    const size_t ro = (size_t)i * NT + j;
    const float4 c0 = *(const float4*)(cd + (size_t)b * 3 * NN2 + ro);
    const float4 c1 = *(const float4*)(cd + ((size_t)b * 3 + 1) * NN2 + ro);
    const float4 c2 = *(const float4*)(cd + ((size_t)b * 3 + 2) * NN2 + ro);
#pragma unroll
    for (int h = 0; h < HH; h++) {
        const float w0 = __ldg(rel_w + h * 3 + 0) * L2E;
        const float w1 = __ldg(rel_w + h * 3 + 1) * L2E;
        const float w2 = __ldg(rel_w + h * 3 + 2) * L2E;
        const float rb = __ldg(rel_b + h) * L2E;
        float4 o;
        o.x = w0 * c0.x + w1 * c1.x + w2 * c2.x + rb;
        o.y = w0 * c0.y + w1 * c1.y + w2 * c2.y + rb;
        o.z = w0 * c0.z + w1 * c1.z + w2 * c2.z + rb;
        o.w = w0 * c0.w + w1 * c1.w + w2 * c2.w + rb;
        *(float4*)(bias32 + ((size_t)(b * HH + h) * NT + i) * NT + j) = o;
    }
}

// ---------------------------------------------------------------------------
// Split-fp16 GEMM body (R10-proven): C = (Ahi+Alo)@(Bhi+Blo)^T via 3 mma.
// ---------------------------------------------------------------------------
template <bool OUT16>
__device__ __forceinline__ void hgemm3_body(
    const __half* __restrict__ Ahi, const __half* __restrict__ Alo,
    const __half* __restrict__ Bhi, const __half* __restrict__ Blo,
    const float* __restrict__ bias, void* __restrict__ Cv, int ldc,
    int bx, int by, char* sh)
{
    __half* AH = (__half*)sh;
    __half* AL = (__half*)(sh + 18432);
    __half* BH = (__half*)(sh + 36864);
    __half* BL = (__half*)(sh + 46080);

    const int tid = threadIdx.x;
    const int lane = tid & 31, w = tid >> 5;
    const int g = lane >> 2, t = lane & 3;
    const int m0 = by << 7, n0 = bx << 6;

    float acc[8][4] = {};

    for (int kc = 0; kc < DD; kc += 64) {
#pragma unroll
        for (int i = 0; i < 4; i++) {
            const int fi = tid + (i << 8);
            const int row = fi >> 3, c8 = (fi & 7) << 3;
            const size_t go = (size_t)(m0 + row) * DD + kc + c8;
            *(float4*)&AH[row * 72 + c8] = *(const float4*)(Ahi + go);
            *(float4*)&AL[row * 72 + c8] = *(const float4*)(Alo + go);
        }
#pragma unroll
        for (int i = 0; i < 2; i++) {
            const int fi = tid + (i << 8);
            const int row = fi >> 3, c8 = (fi & 7) << 3;
            const size_t go = (size_t)(n0 + row) * DD + kc + c8;
            *(float4*)&BH[row * 72 + c8] = *(const float4*)(Bhi + go);
            *(float4*)&BL[row * 72 + c8] = *(const float4*)(Blo + go);
        }
        __syncthreads();
        const uint32_t* ah32 = (const uint32_t*)AH;
        const uint32_t* al32 = (const uint32_t*)AL;
        const uint32_t* bh32 = (const uint32_t*)BH;
        const uint32_t* bl32 = (const uint32_t*)BL;
#pragma unroll
        for (int kk = 0; kk < 4; kk++) {
            const int i0r = (w * 16 + g) * 36 + kk * 8 + t;
            const int i1r = (w * 16 + g + 8) * 36 + kk * 8 + t;
            const uint32_t ah0 = ah32[i0r], ah1 = ah32[i1r];
            const uint32_t ah2 = ah32[i0r + 4], ah3 = ah32[i1r + 4];
            const uint32_t al0 = al32[i0r], al1 = al32[i1r];
            const uint32_t al2 = al32[i0r + 4], al3 = al32[i1r + 4];
#pragma unroll
            for (int nn = 0; nn < 8; nn++) {
                const int bi = (nn * 8 + g) * 36 + kk * 8 + t;
                const uint32_t bh0 = bh32[bi], bh1 = bh32[bi + 4];
                const uint32_t bl0 = bl32[bi], bl1 = bl32[bi + 4];
                mma_f16(acc[nn], ah0, ah1, ah2, ah3, bh0, bh1);
                mma_f16(acc[nn], ah0, ah1, ah2, ah3, bl0, bl1);
                mma_f16(acc[nn], al0, al1, al2, al3, bh0, bh1);
            }
        }
        __syncthreads();
    }

    const int row0 = m0 + w * 16 + g, row1 = row0 + 8;
    if (OUT16) {
        __half* C = (__half*)Cv;
#pragma unroll
        for (int nn = 0; nn < 8; nn++) {
            const int col = n0 + nn * 8 + 2 * t;
            *(uint32_t*)(C + (size_t)row0 * ldc + col) = pack2h(acc[nn][0], acc[nn][1]);
            *(uint32_t*)(C + (size_t)row1 * ldc + col) = pack2h(acc[nn][2], acc[nn][3]);
        }
    } else {
        float* C = (float*)Cv;
#pragma unroll
        for (int nn = 0; nn < 8; nn++) {
            const int col = n0 + nn * 8 + 2 * t;
            const float2 bb = *(const float2*)(bias + col);
            *(float2*)(C + (size_t)row0 * ldc + col) =
                make_float2(acc[nn][0] + bb.x, acc[nn][1] + bb.y);
            *(float2*)(C + (size_t)row1 * ldc + col) =
                make_float2(acc[nn][2] + bb.x, acc[nn][3] + bb.y);
        }
    }
}

// ---------------------------------------------------------------------------
// Fused front-end (exact R13 config): 1536 GEMM + 16384 bias blocks,
// Bresenham stripe g(i)=i*3/35, default launch bounds.
// ---------------------------------------------------------------------------
#define GEMM_BLOCKS 1536
#define BIAS_BLOCKS 16384
#define FUSED_TOTAL (GEMM_BLOCKS + BIAS_BLOCKS)

__global__ __launch_bounds__(256) void fused_pre_kernel(
    const float* __restrict__ cd, const float* __restrict__ rel_w,
    const float* __restrict__ rel_b, float* __restrict__ bias32,
    const __half* __restrict__ xhi, const __half* __restrict__ xlo,
    const __half* __restrict__ wqh, const __half* __restrict__ wql,
    __half* __restrict__ qkv16)
{
    extern __shared__ char sh[];
    const int i = blockIdx.x;
    const int gi  = (i * 3) / 35;        // gemm blocks before i
    const int gi1 = ((i + 1) * 3) / 35;
    if (gi1 > gi && gi < GEMM_BLOCKS) {
        hgemm3_body<true>(xhi, xlo, wqh, wql, nullptr, qkv16, QKVC,
                          gi % 24, gi / 24, sh);
    } else {
        const int bid = i - gi1;
        if (bid < BIAS_BLOCKS)
            bias_body(bid, cd, rel_w, rel_b, bias32);
    }
}

// standalone hgemm3 (out-projection)
template <bool OUT16>
__global__ __launch_bounds__(256) void hgemm3_kernel(
    const __half* __restrict__ Ahi, const __half* __restrict__ Alo,
    const __half* __restrict__ Bhi, const __half* __restrict__ Blo,
    const float* __restrict__ bias, void* __restrict__ Cv, int ldc)
{
    extern __shared__ char sh[];
    hgemm3_body<OUT16>(Ahi, Alo, Bhi, Blo, bias, Cv, ldc,
                       blockIdx.x, blockIdx.y, sh);
}

// ---------------------------------------------------------------------------
// V transpose: qkv16 v-part -> v16t [b,h,d,n]
// ---------------------------------------------------------------------------
__global__ __launch_bounds__(256) void vtrans_kernel(
    const __half* __restrict__ qkv16, __half* __restrict__ v16t)
{
    __shared__ __half vs[64 * 72];
    const int tid = threadIdx.x;
    const int h = blockIdx.x & 7;
    const int n0 = (blockIdx.x >> 3) << 6;
    const int b = blockIdx.y;

#pragma unroll
    for (int it = 0; it < 8; it++) {
        const int idx = tid + (it << 8);
        const int j = idx >> 5, d2 = (idx & 31) << 1;
        const __half2 v = *(const __half2*)(qkv16
            + (size_t)(b * NT + n0 + j) * QKVC + 2 * INNER + h * DHH + d2);
        vs[d2 * 72 + j] = __low2half(v);
        vs[(d2 + 1) * 72 + j] = __high2half(v);
    }
    __syncthreads();
#pragma unroll
    for (int it = 0; it < 8; it++) {
        const int idx = tid + (it << 8);
        const int d = idx >> 5, j2 = (idx & 31) << 1;
        *(uint32_t*)(v16t + ((size_t)((b * HH + h) * DHH + d)) * NT + n0 + j2) =
            *(const uint32_t*)&vs[d * 72 + j2];
    }
}

// ---------------------------------------------------------------------------
// Fused flash attention: R12 structure + ldmatrix.x4 B-fragment loads.
// smem: KS 2x9216 @0, VT 2x9216 @18432, BS 2x34816 @36864, mbar @106496
// ---------------------------------------------------------------------------
#define KS_B 0
#define KS_SZB 9216
#define VT_B 18432
#define VT_SZB 9216
#define BS_B 36864
#define BS_SZB 34816
#define MB_B 106496
#define ATTN_SMEM_BYTES 106528

__device__ __forceinline__ void copy_kv(int idx, int jn, int buf, int b, int h,
                                        const __half* qkv16, const __half* v16t,
                                        char* smc, uint32_t mbar) {
    mbar_expect(mbar, 128u);
    if (idx < 64) {
        const __half* src = qkv16 + (size_t)(b * NT + jn + idx) * QKVC
                            + INNER + h * DHH;
        bulk_cp(smaddr(smc + KS_B + buf * KS_SZB + idx * 144), src, 128u, mbar);
    } else {
        const int r = idx - 64;
        const __half* src = v16t + ((size_t)((b * HH + h) * DHH + r)) * NT + jn;
        bulk_cp(smaddr(smc + VT_B + buf * VT_SZB + r * 144), src, 128u, mbar);
    }
}

__device__ __forceinline__ void copy_bs(int idx, int jn, int buf, int b, int h,
                                        int i0, const float* bias32,
                                        char* smc, uint32_t mbar) {
    mbar_expect(mbar, 256u);
    const float* src = bias32 + ((size_t)(b * HH + h) * NT + i0 + idx) * NT + jn;
    bulk_cp(smaddr(smc + BS_B + buf * BS_SZB + idx * 272), src, 256u, mbar);
}

__global__ __launch_bounds__(256, 2) void attn_kernel(
    const __half* __restrict__ qkv16, const __half* __restrict__ v16t,
    const float* __restrict__ bias32, __half* __restrict__ ohi,
    __half* __restrict__ olo)
{
    extern __shared__ char smc[];
    const int tid = threadIdx.x;
    const int lane = tid & 31, w = tid >> 5;
    const int g = lane >> 2, t = lane & 3;
    const int h = blockIdx.x & 7;
    const int i0 = (blockIdx.x >> 3) << 7;
    const int b = blockIdx.y;

    // ldmatrix per-lane offset: rows 0-7 -> matrices 0/1 (n 0-7), rows for
    // matrices 2/3 are n 8-15; lanes 8-15 & 24-31 take the +16B k-half.
    const int nlocal = (lane & 7) + ((lane >> 4) << 3);
    const int ksel = (lane >> 3) & 1;
    const uint32_t lm_off = (uint32_t)(nlocal * 144 + ksel * 16);

    const uint32_t mb_kv0 = smaddr(smc + MB_B);
    const uint32_t mb_kv1 = mb_kv0 + 8;
    const uint32_t mb_bs0 = mb_kv0 + 16;
    const uint32_t mb_bs1 = mb_kv0 + 24;

    if (tid == 0) {
        asm volatile("mbarrier.init.shared.b64 [%0], %1;" :: "r"(mb_kv0), "r"(128u) : "memory");
        asm volatile("mbarrier.init.shared.b64 [%0], %1;" :: "r"(mb_kv1), "r"(128u) : "memory");
        asm volatile("mbarrier.init.shared.b64 [%0], %1;" :: "r"(mb_bs0), "r"(128u) : "memory");
        asm volatile("mbarrier.init.shared.b64 [%0], %1;" :: "r"(mb_bs1), "r"(128u) : "memory");
        asm volatile("fence.proxy.async.shared::cta;" ::: "memory");
    }
    __syncthreads();

    if (tid < 128) {
        copy_kv(tid, 0, 0, b, h, qkv16, v16t, smc, mb_kv0);
        copy_kv(tid, 64, 1, b, h, qkv16, v16t, smc, mb_kv1);
    } else {
        copy_bs(tid - 128, 0, 0, b, h, i0, bias32, smc, mb_bs0);
        copy_bs(tid - 128, 64, 1, b, h, i0, bias32, smc, mb_bs1);
    }

    // ---- Q A-fragments from qkv16 ----
    uint32_t qa[4][4];
#pragma unroll
    for (int kk = 0; kk < 4; kk++)
#pragma unroll
        for (int r = 0; r < 4; r++) {
            const int row = i0 + w * 16 + g + ((r & 1) ? 8 : 0);
            const int col = h * DHH + kk * 16 + 2 * t + ((r & 2) ? 8 : 0);
            qa[kk][r] = *(const uint32_t*)(qkv16 + (size_t)(b * NT + row) * QKVC + col);
        }

    float m0 = -1e30f, m1 = -1e30f, l0 = 0.f, l1 = 0.f;
    float o[8][4];
#pragma unroll
    for (int dd = 0; dd < 8; dd++)
        o[dd][0] = o[dd][1] = o[dd][2] = o[dd][3] = 0.f;

    const int rl0 = w * 16 + g, rl1 = rl0 + 8;

    for (int jt = 0; jt < NJT; jt++) {
        const int buf = jt & 1;
        const int par = (jt >> 1) & 1;
        const uint32_t ks_lm = smaddr(smc + KS_B + buf * KS_SZB) + lm_off;
        const uint32_t vt_lm = smaddr(smc + VT_B + buf * VT_SZB) + lm_off;
        const float* bsf = (const float*)(smc + BS_B + buf * BS_SZB);

        mbar_wait(buf ? mb_kv1 : mb_kv0, par);

        // ---- S = Q K^T (B-frags via ldmatrix.x4: 2 nn per load) ----
        float s_[8][4];
#pragma unroll
        for (int nn = 0; nn < 8; nn++)
            s_[nn][0] = s_[nn][1] = s_[nn][2] = s_[nn][3] = 0.f;
#pragma unroll
        for (int kk = 0; kk < 4; kk++) {
#pragma unroll
            for (int p = 0; p < 4; p++) {
                uint32_t bm[4];
                ldsm_x4(bm, ks_lm + p * 2304 + kk * 32);
                mma_f16(s_[2 * p], qa[kk][0], qa[kk][1], qa[kk][2], qa[kk][3],
                        bm[0], bm[1]);
                mma_f16(s_[2 * p + 1], qa[kk][0], qa[kk][1], qa[kk][2], qa[kk][3],
                        bm[2], bm[3]);
            }
        }

        mbar_wait(buf ? mb_bs1 : mb_bs0, par);

        // ---- logits in log2 domain ----
        float mx0 = -1e30f, mx1 = -1e30f;
#pragma unroll
        for (int nn = 0; nn < 8; nn++) {
            const int c = nn * 8 + 2 * t;
            const float2 bf0 = *(const float2*)&bsf[rl0 * 68 + c];
            const float2 bf1 = *(const float2*)&bsf[rl1 * 68 + c];
            s_[nn][0] = fmaf(s_[nn][0], SCALE_L2E, bf0.x);
            s_[nn][1] = fmaf(s_[nn][1], SCALE_L2E, bf0.y);
            s_[nn][2] = fmaf(s_[nn][2], SCALE_L2E, bf1.x);
            s_[nn][3] = fmaf(s_[nn][3], SCALE_L2E, bf1.y);
            mx0 = fmaxf(mx0, fmaxf(s_[nn][0], s_[nn][1]));
            mx1 = fmaxf(mx1, fmaxf(s_[nn][2], s_[nn][3]));
        }
#pragma unroll
        for (int off = 1; off <= 2; off <<= 1) {
            mx0 = fmaxf(mx0, __shfl_xor_sync(0xffffffffu, mx0, off));
            mx1 = fmaxf(mx1, __shfl_xor_sync(0xffffffffu, mx1, off));
        }
        const float mn0 = fmaxf(m0, mx0), mn1 = fmaxf(m1, mx1);
        const float fac0 = ex2f(m0 - mn0), fac1 = ex2f(m1 - mn1);
        m0 = mn0; m1 = mn1;
        float rs0 = 0.f, rs1 = 0.f;
#pragma unroll
        for (int nn = 0; nn < 8; nn++) {
            s_[nn][0] = ex2f(s_[nn][0] - mn0);
            s_[nn][1] = ex2f(s_[nn][1] - mn0);
            s_[nn][2] = ex2f(s_[nn][2] - mn1);
            s_[nn][3] = ex2f(s_[nn][3] - mn1);
            rs0 += s_[nn][0] + s_[nn][1];
            rs1 += s_[nn][2] + s_[nn][3];
        }
        // deferred: l stays lane-partial (quad reduction in epilogue)
        l0 = l0 * fac0 + rs0;
        l1 = l1 * fac1 + rs1;
#pragma unroll
        for (int dd = 0; dd < 8; dd++) {
            o[dd][0] *= fac0; o[dd][1] *= fac0;
            o[dd][2] *= fac1; o[dd][3] *= fac1;
        }

        // ---- O += P V (B-frags via ldmatrix.x4: 2 dd per load) ----
#pragma unroll
        for (int jj = 0; jj < 4; jj++) {
            const uint32_t a0 = pack2h(s_[2 * jj][0], s_[2 * jj][1]);
            const uint32_t a1 = pack2h(s_[2 * jj][2], s_[2 * jj][3]);
            const uint32_t a2 = pack2h(s_[2 * jj + 1][0], s_[2 * jj + 1][1]);
            const uint32_t a3 = pack2h(s_[2 * jj + 1][2], s_[2 * jj + 1][3]);
#pragma unroll
            for (int p = 0; p < 4; p++) {
                uint32_t bm[4];
                ldsm_x4(bm, vt_lm + p * 2304 + jj * 32);
                mma_f16(o[2 * p], a0, a1, a2, a3, bm[0], bm[1]);
                mma_f16(o[2 * p + 1], a0, a1, a2, a3, bm[2], bm[3]);
            }
        }

        __syncthreads();   // KV + bias buffers fully consumed by all warps

        if (jt + 2 < NJT) {
            const int jn = (jt + 2) << 6;
            if (tid < 128)
                copy_kv(tid, jn, buf, b, h, qkv16, v16t, smc,
                        buf ? mb_kv1 : mb_kv0);
            else
                copy_bs(tid - 128, jn, buf, b, h, i0, bias32, smc,
                        buf ? mb_bs1 : mb_bs0);
        }
    }

    // ---- epilogue: quad-reduce l, normalize + split-write O hi/lo ----
    l0 += __shfl_xor_sync(0xffffffffu, l0, 1);
    l0 += __shfl_xor_sync(0xffffffffu, l0, 2);
    l1 += __shfl_xor_sync(0xffffffffu, l1, 1);
    l1 += __shfl_xor_sync(0xffffffffu, l1, 2);
    const float inv0 = 1.0f / l0, inv1 = 1.0f / l1;
    const int row0 = i0 + rl0, row1 = i0 + rl1;
#pragma unroll
    for (int dd = 0; dd < 8; dd++) {
        const int col = h * DHH + dd * 8 + 2 * t;
        const float v00 = o[dd][0] * inv0, v01 = o[dd][1] * inv0;
        const float v10 = o[dd][2] * inv1, v11 = o[dd][3] * inv1;
        const __half2 h0 = __float22half2_rn(make_float2(v00, v01));
        const __half2 h1 = __float22half2_rn(make_float2(v10, v11));
        const float2 hf0 = __half22float2(h0);
        const float2 hf1 = __half22float2(h1);
        const __half2 q0 = __float22half2_rn(make_float2(v00 - hf0.x, v01 - hf0.y));
        const __half2 q1 = __float22half2_rn(make_float2(v10 - hf1.x, v11 - hf1.y));
        *(__half2*)(ohi + (size_t)(b * NT + row0) * INNER + col) = h0;
        *(__half2*)(ohi + (size_t)(b * NT + row1) * INNER + col) = h1;
        *(__half2*)(olo + (size_t)(b * NT + row0) * INNER + col) = q0;
        *(__half2*)(olo + (size_t)(b * NT + row1) * INNER + col) = q1;
    }
}

// ---------------------------------------------------------------------------
extern "C" void kernel_launch(void* const* d_in, const int* in_sizes, int n_in,
                              void* d_out, int out_size)
{
    const float* x     = (const float*)d_in[0];
    const float* cd    = (const float*)d_in[1];
    const float* Wqkv  = (const float*)d_in[2];
    const float* Wout  = (const float*)d_in[3];
    const float* bout  = (const float*)d_in[4];
    const float* rel_w = (const float*)d_in[5];
    const float* rel_b = (const float*)d_in[6];
    float* out = (float*)d_out;

    __half *xhi, *xlo, *wqh, *wql, *woh, *wol, *qkv16, *v16t, *ohi, *olo;
    float *bias32;
    cudaGetSymbolAddress((void**)&xhi, g_xhi);
    cudaGetSymbolAddress((void**)&xlo, g_xlo);
    cudaGetSymbolAddress((void**)&wqh, g_wqh);
    cudaGetSymbolAddress((void**)&wql, g_wql);
    cudaGetSymbolAddress((void**)&woh, g_woh);
    cudaGetSymbolAddress((void**)&wol, g_wol);
    cudaGetSymbolAddress((void**)&qkv16, g_qkv16);
    cudaGetSymbolAddress((void**)&v16t, g_v16t);
    cudaGetSymbolAddress((void**)&bias32, g_bias32);
    cudaGetSymbolAddress((void**)&ohi, g_ohi);
    cudaGetSymbolAddress((void**)&olo, g_olo);

    cudaFuncSetAttribute(attn_kernel, cudaFuncAttributeMaxDynamicSharedMemorySize,
                         ATTN_SMEM_BYTES);
    cudaFuncSetAttribute(fused_pre_kernel,
                         cudaFuncAttributeMaxDynamicSharedMemorySize, 55296);
    cudaFuncSetAttribute(hgemm3_kernel<false>,
                         cudaFuncAttributeMaxDynamicSharedMemorySize, 55296);

    dim3 blk(256);
    // split x and weights to hi/lo fp16
    cvt_x_kernel<<<(BB * NT * DD) / (256 * 4), blk>>>(x, xhi, xlo);
    cvt_w_kernel<<<(QKVC * DD) / 256, blk>>>(Wqkv, wqh, wql, QKVC);
    cvt_w_kernel<<<(DD * DD) / 256, blk>>>(Wout, woh, wol, DD);
    // fused: bias32 (conv1x1 * log2e) blocks interleaved with qkv GEMM blocks
    fused_pre_kernel<<<FUSED_TOTAL, blk, 55296>>>(
        cd, rel_w, rel_b, bias32, xhi, xlo, wqh, wql, qkv16);
    // v transpose per head
    vtrans_kernel<<<dim3(HH * (NT / 64), BB), blk>>>(qkv16, v16t);
    // fused attention -> split O
    attn_kernel<<<dim3(HH * (NT / 128), BB), blk, ATTN_SMEM_BYTES>>>(
        qkv16, v16t, bias32, ohi, olo);
    // out = O @ Wout + bout  (split-fp16, fp32 out)
    hgemm3_kernel<false><<<dim3(DD / 64, (BB * NT) / 128), blk, 55296>>>(
        ohi, olo, woh, wol, bout, out, DD);
}

// round 17
// speedup vs baseline: 1.1183x; 1.0487x over previous
#include <cuda_runtime.h>
#include <cuda_fp16.h>
#include <cstdint>

#define BB 4
#define NT 2048
#define DD 512
#define HH 8
#define DHH 64
#define INNER 512
#define QKVC 1536
#define NJT 32            // 2048/64 j-tiles
#define L2E 1.44269504f
#define SCALE_L2E (0.125f * 1.44269504f)
#define BQ_SCALE 1024.0f
#define BQ_INV 0.0009765625f

// Scratch (device globals — no cudaMalloc allowed)
static __device__ __half g_xhi[(size_t)BB * NT * DD];
static __device__ __half g_xlo[(size_t)BB * NT * DD];
static __device__ __half g_wqh[(size_t)QKVC * DD];   // [n][k]
static __device__ __half g_wql[(size_t)QKVC * DD];
static __device__ __half g_woh[(size_t)DD * DD];     // [n][k]
static __device__ __half g_wol[(size_t)DD * DD];
static __device__ __half g_qkv16[(size_t)BB * NT * QKVC];    // fp16 qkv
static __device__ __half g_v16t[(size_t)BB * HH * DHH * NT]; // [b,h,d,n]
static __device__ short  g_bias16i[(size_t)BB * HH * NT * NT];// q10(bias*l2e)
static __device__ __half g_ohi[(size_t)BB * NT * INNER];
static __device__ __half g_olo[(size_t)BB * NT * INNER];

// ---------------------------------------------------------------------------
// helpers
// ---------------------------------------------------------------------------
__device__ __forceinline__ uint32_t smaddr(const void* p) {
    uint32_t a;
    asm("{.reg .u64 t; cvta.to.shared.u64 t, %1; cvt.u32.u64 %0, t;}"
        : "=r"(a) : "l"(p));
    return a;
}

__device__ __forceinline__ uint32_t pack2h(float lo, float hi) {
    uint32_t d;
    asm("cvt.rn.f16x2.f32 %0, %1, %2;" : "=r"(d) : "f"(hi), "f"(lo));
    return d;
}

__device__ __forceinline__ uint32_t pack2s(float lo, float hi) {
    short a, b;
    asm("cvt.rni.sat.s16.f32 %0, %1;" : "=h"(a) : "f"(lo * BQ_SCALE));
    asm("cvt.rni.sat.s16.f32 %0, %1;" : "=h"(b) : "f"(hi * BQ_SCALE));
    return (uint32_t)(uint16_t)a | ((uint32_t)(uint16_t)b << 16);
}

__device__ __forceinline__ float ex2f(float x) {
    float y;
    asm("ex2.approx.f32 %0, %1;" : "=f"(y) : "f"(x));
    return y;
}

__device__ __forceinline__ void mma_f16(float c[4], uint32_t a0, uint32_t a1,
                                        uint32_t a2, uint32_t a3,
                                        uint32_t b0, uint32_t b1) {
    asm volatile(
        "mma.sync.aligned.m16n8k16.row.col.f32.f16.f16.f32 "
        "{%0,%1,%2,%3}, {%4,%5,%6,%7}, {%8,%9}, {%0,%1,%2,%3};"
        : "+f"(c[0]), "+f"(c[1]), "+f"(c[2]), "+f"(c[3])
        : "r"(a0), "r"(a1), "r"(a2), "r"(a3), "r"(b0), "r"(b1));
}

__device__ __forceinline__ void ldsm_x4(uint32_t r[4], uint32_t addr) {
    asm volatile(
        "ldmatrix.sync.aligned.m8n8.x4.shared.b16 {%0,%1,%2,%3}, [%4];"
        : "=r"(r[0]), "=r"(r[1]), "=r"(r[2]), "=r"(r[3]) : "r"(addr));
}

__device__ __forceinline__ void bulk_cp(uint32_t dst, const void* src,
                                        uint32_t bytes, uint32_t mbar) {
    asm volatile(
        "cp.async.bulk.shared::cta.global.mbarrier::complete_tx::bytes "
        "[%0], [%1], %2, [%3];"
        :: "r"(dst), "l"(src), "r"(bytes), "r"(mbar) : "memory");
}

__device__ __forceinline__ void mbar_expect(uint32_t mbar, uint32_t bytes) {
    asm volatile("mbarrier.arrive.expect_tx.shared.b64 _, [%0], %1;"
                 :: "r"(mbar), "r"(bytes) : "memory");
}

__device__ __forceinline__ void mbar_wait(uint32_t mbar, uint32_t parity) {
    uint32_t done;
    do {
        asm volatile(
            "{.reg .pred p; "
            "mbarrier.try_wait.parity.acquire.cta.shared::cta.b64 p, [%1], %2, 0x989680; "
            "selp.b32 %0,1,0,p;}"
            : "=r"(done) : "r"(mbar), "r"(parity) : "memory");
    } while (!done);
}

// ---------------------------------------------------------------------------
// split conversion kernels
// ---------------------------------------------------------------------------
__global__ __launch_bounds__(256) void cvt_x_kernel(
    const float* __restrict__ x, __half* __restrict__ xhi,
    __half* __restrict__ xlo)
{
    const size_t i = ((size_t)blockIdx.x * 256 + threadIdx.x) * 4;
    const float4 v = *(const float4*)(x + i);
    const __half2 h0 = __float22half2_rn(make_float2(v.x, v.y));
    const __half2 h1 = __float22half2_rn(make_float2(v.z, v.w));
    const float2 f0 = __half22float2(h0);
    const float2 f1 = __half22float2(h1);
    const __half2 l0 = __float22half2_rn(make_float2(v.x - f0.x, v.y - f0.y));
    const __half2 l1 = __float22half2_rn(make_float2(v.z - f1.x, v.w - f1.y));
    *(__half2*)(xhi + i) = h0;
    *(__half2*)(xhi + i + 2) = h1;
    *(__half2*)(xlo + i) = l0;
    *(__half2*)(xlo + i + 2) = l1;
}

// W [K rows][N cols] -> wh/wl [n][k], split
__global__ __launch_bounds__(256) void cvt_w_kernel(
    const float* __restrict__ W, __half* __restrict__ wh,
    __half* __restrict__ wl, int Ncols)
{
    const int idx = blockIdx.x * 256 + threadIdx.x;
    const int n = idx >> 9, k = idx & 511;
    const float v = W[(size_t)k * Ncols + n];
    const __half h = __float2half_rn(v);
    wh[(size_t)n * DD + k] = h;
    wl[(size_t)n * DD + k] = __float2half_rn(v - __half2float(h));
}

// ---------------------------------------------------------------------------
// bias body: q10 int16 of (sum_c rel_w[h,c]*cd[...] + rel_b[h]) * log2e
// ---------------------------------------------------------------------------
__device__ __forceinline__ void bias_body(
    int bid, const float* __restrict__ cd, const float* __restrict__ rel_w,
    const float* __restrict__ rel_b, short* __restrict__ bias16i)
{
    const int b = bid >> 12;                       // 4096 blocks per batch
    const size_t pos = (size_t)(bid & 4095) * 256 + threadIdx.x;
    const int i = (int)(pos >> 9);
    const int j = (int)(pos & 511) << 2;
    const size_t NN2 = (size_t)NT * NT;
    const size_t ro = (size_t)i * NT + j;
    const float4 c0 = *(const float4*)(cd + (size_t)b * 3 * NN2 + ro);
    const float4 c1 = *(const float4*)(cd + ((size_t)b * 3 + 1) * NN2 + ro);
    const float4 c2 = *(const float4*)(cd + ((size_t)b * 3 + 2) * NN2 + ro);
#pragma unroll
    for (int h = 0; h < HH; h++) {
        const float w0 = __ldg(rel_w + h * 3 + 0) * L2E;
        const float w1 = __ldg(rel_w + h * 3 + 1) * L2E;
        const float w2 = __ldg(rel_w + h * 3 + 2) * L2E;
        const float rb = __ldg(rel_b + h) * L2E;
        uint2 o;
        o.x = pack2s(w0 * c0.x + w1 * c1.x + w2 * c2.x + rb,
                     w0 * c0.y + w1 * c1.y + w2 * c2.y + rb);
        o.y = pack2s(w0 * c0.z + w1 * c1.z + w2 * c2.z + rb,
                     w0 * c0.w + w1 * c1.w + w2 * c2.w + rb);
        *(uint2*)(bias16i + ((size_t)(b * HH + h) * NT + i) * NT + j) = o;
    }
}

// ---------------------------------------------------------------------------
// Split-fp16 GEMM body (R10-proven): C = (Ahi+Alo)@(Bhi+Blo)^T via 3 mma.
// ---------------------------------------------------------------------------
template <bool OUT16>
__device__ __forceinline__ void hgemm3_body(
    const __half* __restrict__ Ahi, const __half* __restrict__ Alo,
    const __half* __restrict__ Bhi, const __half* __restrict__ Blo,
    const float* __restrict__ bias, void* __restrict__ Cv, int ldc,
    int bx, int by, char* sh)
{
    __half* AH = (__half*)sh;
    __half* AL = (__half*)(sh + 18432);
    __half* BH = (__half*)(sh + 36864);
    __half* BL = (__half*)(sh + 46080);

    const int tid = threadIdx.x;
    const int lane = tid & 31, w = tid >> 5;
    const int g = lane >> 2, t = lane & 3;
    const int m0 = by << 7, n0 = bx << 6;

    float acc[8][4] = {};

    for (int kc = 0; kc < DD; kc += 64) {
#pragma unroll
        for (int i = 0; i < 4; i++) {
            const int fi = tid + (i << 8);
            const int row = fi >> 3, c8 = (fi & 7) << 3;
            const size_t go = (size_t)(m0 + row) * DD + kc + c8;
            *(float4*)&AH[row * 72 + c8] = *(const float4*)(Ahi + go);
            *(float4*)&AL[row * 72 + c8] = *(const float4*)(Alo + go);
        }
#pragma unroll
        for (int i = 0; i < 2; i++) {
            const int fi = tid + (i << 8);
            const int row = fi >> 3, c8 = (fi & 7) << 3;
            const size_t go = (size_t)(n0 + row) * DD + kc + c8;
            *(float4*)&BH[row * 72 + c8] = *(const float4*)(Bhi + go);
            *(float4*)&BL[row * 72 + c8] = *(const float4*)(Blo + go);
        }
        __syncthreads();
        const uint32_t* ah32 = (const uint32_t*)AH;
        const uint32_t* al32 = (const uint32_t*)AL;
        const uint32_t* bh32 = (const uint32_t*)BH;
        const uint32_t* bl32 = (const uint32_t*)BL;
#pragma unroll
        for (int kk = 0; kk < 4; kk++) {
            const int i0r = (w * 16 + g) * 36 + kk * 8 + t;
            const int i1r = (w * 16 + g + 8) * 36 + kk * 8 + t;
            const uint32_t ah0 = ah32[i0r], ah1 = ah32[i1r];
            const uint32_t ah2 = ah32[i0r + 4], ah3 = ah32[i1r + 4];
            const uint32_t al0 = al32[i0r], al1 = al32[i1r];
            const uint32_t al2 = al32[i0r + 4], al3 = al32[i1r + 4];
#pragma unroll
            for (int nn = 0; nn < 8; nn++) {
                const int bi = (nn * 8 + g) * 36 + kk * 8 + t;
                const uint32_t bh0 = bh32[bi], bh1 = bh32[bi + 4];
                const uint32_t bl0 = bl32[bi], bl1 = bl32[bi + 4];
                mma_f16(acc[nn], ah0, ah1, ah2, ah3, bh0, bh1);
                mma_f16(acc[nn], ah0, ah1, ah2, ah3, bl0, bl1);
                mma_f16(acc[nn], al0, al1, al2, al3, bh0, bh1);
            }
        }
        __syncthreads();
    }

    const int row0 = m0 + w * 16 + g, row1 = row0 + 8;
    if (OUT16) {
        __half* C = (__half*)Cv;
#pragma unroll
        for (int nn = 0; nn < 8; nn++) {
            const int col = n0 + nn * 8 + 2 * t;
            *(uint32_t*)(C + (size_t)row0 * ldc + col) = pack2h(acc[nn][0], acc[nn][1]);
            *(uint32_t*)(C + (size_t)row1 * ldc + col) = pack2h(acc[nn][2], acc[nn][3]);
        }
    } else {
        float* C = (float*)Cv;
#pragma unroll
        for (int nn = 0; nn < 8; nn++) {
            const int col = n0 + nn * 8 + 2 * t;
            const float2 bb = *(const float2*)(bias + col);
            *(float2*)(C + (size_t)row0 * ldc + col) =
                make_float2(acc[nn][0] + bb.x, acc[nn][1] + bb.y);
            *(float2*)(C + (size_t)row1 * ldc + col) =
                make_float2(acc[nn][2] + bb.x, acc[nn][3] + bb.y);
        }
    }
}

// ---------------------------------------------------------------------------
// Fused front-end (R13/R16 config): 1536 GEMM + 16384 bias blocks,
// Bresenham stripe g(i)=i*3/35, default launch bounds.
// ---------------------------------------------------------------------------
#define GEMM_BLOCKS 1536
#define BIAS_BLOCKS 16384
#define FUSED_TOTAL (GEMM_BLOCKS + BIAS_BLOCKS)

__global__ __launch_bounds__(256) void fused_pre_kernel(
    const float* __restrict__ cd, const float* __restrict__ rel_w,
    const float* __restrict__ rel_b, short* __restrict__ bias16i,
    const __half* __restrict__ xhi, const __half* __restrict__ xlo,
    const __half* __restrict__ wqh, const __half* __restrict__ wql,
    __half* __restrict__ qkv16)
{
    extern __shared__ char sh[];
    const int i = blockIdx.x;
    const int gi  = (i * 3) / 35;        // gemm blocks before i
    const int gi1 = ((i + 1) * 3) / 35;
    if (gi1 > gi && gi < GEMM_BLOCKS) {
        hgemm3_body<true>(xhi, xlo, wqh, wql, nullptr, qkv16, QKVC,
                          gi % 24, gi / 24, sh);
    } else {
        const int bid = i - gi1;
        if (bid < BIAS_BLOCKS)
            bias_body(bid, cd, rel_w, rel_b, bias16i);
    }
}

// standalone hgemm3 (out-projection)
template <bool OUT16>
__global__ __launch_bounds__(256) void hgemm3_kernel(
    const __half* __restrict__ Ahi, const __half* __restrict__ Alo,
    const __half* __restrict__ Bhi, const __half* __restrict__ Blo,
    const float* __restrict__ bias, void* __restrict__ Cv, int ldc)
{
    extern __shared__ char sh[];
    hgemm3_body<OUT16>(Ahi, Alo, Bhi, Blo, bias, Cv, ldc,
                       blockIdx.x, blockIdx.y, sh);
}

// ---------------------------------------------------------------------------
// V transpose: qkv16 v-part -> v16t [b,h,d,n]
// ---------------------------------------------------------------------------
__global__ __launch_bounds__(256) void vtrans_kernel(
    const __half* __restrict__ qkv16, __half* __restrict__ v16t)
{
    __shared__ __half vs[64 * 72];
    const int tid = threadIdx.x;
    const int h = blockIdx.x & 7;
    const int n0 = (blockIdx.x >> 3) << 6;
    const int b = blockIdx.y;

#pragma unroll
    for (int it = 0; it < 8; it++) {
        const int idx = tid + (it << 8);
        const int j = idx >> 5, d2 = (idx & 31) << 1;
        const __half2 v = *(const __half2*)(qkv16
            + (size_t)(b * NT + n0 + j) * QKVC + 2 * INNER + h * DHH + d2);
        vs[d2 * 72 + j] = __low2half(v);
        vs[(d2 + 1) * 72 + j] = __high2half(v);
    }
    __syncthreads();
#pragma unroll
    for (int it = 0; it < 8; it++) {
        const int idx = tid + (it << 8);
        const int d = idx >> 5, j2 = (idx & 31) << 1;
        *(uint32_t*)(v16t + ((size_t)((b * HH + h) * DHH + d)) * NT + n0 + j2) =
            *(const uint32_t*)&vs[d * 72 + j2];
    }
}

// ---------------------------------------------------------------------------
// Fused flash attention: R16 structure (ldmatrix B-frags) + int16 bias.
// smem: KS 2x9216 @0, VT 2x9216 @18432, BS 2x18432 @36864, mbar @73728
// ---------------------------------------------------------------------------
#define KS_B 0
#define KS_SZB 9216
#define VT_B 18432
#define VT_SZB 9216
#define BS_B 36864
#define BS_SZB 18432
#define MB_B 73728
#define ATTN_SMEM_BYTES 73760

__device__ __forceinline__ void copy_kv(int idx, int jn, int buf, int b, int h,
                                        const __half* qkv16, const __half* v16t,
                                        char* smc, uint32_t mbar) {
    mbar_expect(mbar, 128u);
    if (idx < 64) {
        const __half* src = qkv16 + (size_t)(b * NT + jn + idx) * QKVC
                            + INNER + h * DHH;
        bulk_cp(smaddr(smc + KS_B + buf * KS_SZB + idx * 144), src, 128u, mbar);
    } else {
        const int r = idx - 64;
        const __half* src = v16t + ((size_t)((b * HH + h) * DHH + r)) * NT + jn;
        bulk_cp(smaddr(smc + VT_B + buf * VT_SZB + r * 144), src, 128u, mbar);
    }
}

__device__ __forceinline__ void copy_bs(int idx, int jn, int buf, int b, int h,
                                        int i0, const short* bias16i,
                                        char* smc, uint32_t mbar) {
    mbar_expect(mbar, 128u);
    const short* src = bias16i + ((size_t)(b * HH + h) * NT + i0 + idx) * NT + jn;
    bulk_cp(smaddr(smc + BS_B + buf * BS_SZB + idx * 144), src, 128u, mbar);
}

__global__ __launch_bounds__(256, 2) void attn_kernel(
    const __half* __restrict__ qkv16, const __half* __restrict__ v16t,
    const short* __restrict__ bias16i, __half* __restrict__ ohi,
    __half* __restrict__ olo)
{
    extern __shared__ char smc[];
    const int tid = threadIdx.x;
    const int lane = tid & 31, w = tid >> 5;
    const int g = lane >> 2, t = lane & 3;
    const int h = blockIdx.x & 7;
    const int i0 = (blockIdx.x >> 3) << 7;
    const int b = blockIdx.y;

    // ldmatrix per-lane offset (R16-proven)
    const int nlocal = (lane & 7) + ((lane >> 4) << 3);
    const int ksel = (lane >> 3) & 1;
    const uint32_t lm_off = (uint32_t)(nlocal * 144 + ksel * 16);

    const uint32_t mb_kv0 = smaddr(smc + MB_B);
    const uint32_t mb_kv1 = mb_kv0 + 8;
    const uint32_t mb_bs0 = mb_kv0 + 16;
    const uint32_t mb_bs1 = mb_kv0 + 24;

    if (tid == 0) {
        asm volatile("mbarrier.init.shared.b64 [%0], %1;" :: "r"(mb_kv0), "r"(128u) : "memory");
        asm volatile("mbarrier.init.shared.b64 [%0], %1;" :: "r"(mb_kv1), "r"(128u) : "memory");
        asm volatile("mbarrier.init.shared.b64 [%0], %1;" :: "r"(mb_bs0), "r"(128u) : "memory");
        asm volatile("mbarrier.init.shared.b64 [%0], %1;" :: "r"(mb_bs1), "r"(128u) : "memory");
        asm volatile("fence.proxy.async.shared::cta;" ::: "memory");
    }
    __syncthreads();

    if (tid < 128) {
        copy_kv(tid, 0, 0, b, h, qkv16, v16t, smc, mb_kv0);
        copy_kv(tid, 64, 1, b, h, qkv16, v16t, smc, mb_kv1);
    } else {
        copy_bs(tid - 128, 0, 0, b, h, i0, bias16i, smc, mb_bs0);
        copy_bs(tid - 128, 64, 1, b, h, i0, bias16i, smc, mb_bs1);
    }

    // ---- Q A-fragments from qkv16 ----
    uint32_t qa[4][4];
#pragma unroll
    for (int kk = 0; kk < 4; kk++)
#pragma unroll
        for (int r = 0; r < 4; r++) {
            const int row = i0 + w * 16 + g + ((r & 1) ? 8 : 0);
            const int col = h * DHH + kk * 16 + 2 * t + ((r & 2) ? 8 : 0);
            qa[kk][r] = *(const uint32_t*)(qkv16 + (size_t)(b * NT + row) * QKVC + col);
        }

    float m0 = -1e30f, m1 = -1e30f, l0 = 0.f, l1 = 0.f;
    float o[8][4];
#pragma unroll
    for (int dd = 0; dd < 8; dd++)
        o[dd][0] = o[dd][1] = o[dd][2] = o[dd][3] = 0.f;

    const int rl0 = w * 16 + g, rl1 = rl0 + 8;

    for (int jt = 0; jt < NJT; jt++) {
        const int buf = jt & 1;
        const int par = (jt >> 1) & 1;
        const uint32_t ks_lm = smaddr(smc + KS_B + buf * KS_SZB) + lm_off;
        const uint32_t vt_lm = smaddr(smc + VT_B + buf * VT_SZB) + lm_off;
        const short2* bsh = (const short2*)(smc + BS_B + buf * BS_SZB);

        mbar_wait(buf ? mb_kv1 : mb_kv0, par);

        // ---- S = Q K^T (B-frags via ldmatrix.x4) ----
        float s_[8][4];
#pragma unroll
        for (int nn = 0; nn < 8; nn++)
            s_[nn][0] = s_[nn][1] = s_[nn][2] = s_[nn][3] = 0.f;
#pragma unroll
        for (int kk = 0; kk < 4; kk++) {
#pragma unroll
            for (int p = 0; p < 4; p++) {
                uint32_t bm[4];
                ldsm_x4(bm, ks_lm + p * 2304 + kk * 32);
                mma_f16(s_[2 * p], qa[kk][0], qa[kk][1], qa[kk][2], qa[kk][3],
                        bm[0], bm[1]);
                mma_f16(s_[2 * p + 1], qa[kk][0], qa[kk][1], qa[kk][2], qa[kk][3],
                        bm[2], bm[3]);
            }
        }

        mbar_wait(buf ? mb_bs1 : mb_bs0, par);

        // ---- logits in log2 domain: S*scale*l2e + i16_bias/1024 ----
        float mx0 = -1e30f, mx1 = -1e30f;
#pragma unroll
        for (int nn = 0; nn < 8; nn++) {
            const short2 q0s = bsh[rl0 * 36 + nn * 4 + t];
            const short2 q1s = bsh[rl1 * 36 + nn * 4 + t];
            s_[nn][0] = fmaf(s_[nn][0], SCALE_L2E, (float)q0s.x * BQ_INV);
            s_[nn][1] = fmaf(s_[nn][1], SCALE_L2E, (float)q0s.y * BQ_INV);
            s_[nn][2] = fmaf(s_[nn][2], SCALE_L2E, (float)q1s.x * BQ_INV);
            s_[nn][3] = fmaf(s_[nn][3], SCALE_L2E, (float)q1s.y * BQ_INV);
            mx0 = fmaxf(mx0, fmaxf(s_[nn][0], s_[nn][1]));
            mx1 = fmaxf(mx1, fmaxf(s_[nn][2], s_[nn][3]));
        }
#pragma unroll
        for (int off = 1; off <= 2; off <<= 1) {
            mx0 = fmaxf(mx0, __shfl_xor_sync(0xffffffffu, mx0, off));
            mx1 = fmaxf(mx1, __shfl_xor_sync(0xffffffffu, mx1, off));
        }
        const float mn0 = fmaxf(m0, mx0), mn1 = fmaxf(m1, mx1);
        const float fac0 = ex2f(m0 - mn0), fac1 = ex2f(m1 - mn1);
        m0 = mn0; m1 = mn1;
        float rs0 = 0.f, rs1 = 0.f;
#pragma unroll
        for (int nn = 0; nn < 8; nn++) {
            s_[nn][0] = ex2f(s_[nn][0] - mn0);
            s_[nn][1] = ex2f(s_[nn][1] - mn0);
            s_[nn][2] = ex2f(s_[nn][2] - mn1);
            s_[nn][3] = ex2f(s_[nn][3] - mn1);
            rs0 += s_[nn][0] + s_[nn][1];
            rs1 += s_[nn][2] + s_[nn][3];
        }
        // deferred: l stays lane-partial (quad reduction in epilogue)
        l0 = l0 * fac0 + rs0;
        l1 = l1 * fac1 + rs1;
#pragma unroll
        for (int dd = 0; dd < 8; dd++) {
            o[dd][0] *= fac0; o[dd][1] *= fac0;
            o[dd][2] *= fac1; o[dd][3] *= fac1;
        }

        // ---- O += P V (B-frags via ldmatrix.x4) ----
#pragma unroll
        for (int jj = 0; jj < 4; jj++) {
            const uint32_t a0 = pack2h(s_[2 * jj][0], s_[2 * jj][1]);
            const uint32_t a1 = pack2h(s_[2 * jj][2], s_[2 * jj][3]);
            const uint32_t a2 = pack2h(s_[2 * jj + 1][0], s_[2 * jj + 1][1]);
            const uint32_t a3 = pack2h(s_[2 * jj + 1][2], s_[2 * jj + 1][3]);
#pragma unroll
            for (int p = 0; p < 4; p++) {
                uint32_t bm[4];
                ldsm_x4(bm, vt_lm + p * 2304 + jj * 32);
                mma_f16(o[2 * p], a0, a1, a2, a3, bm[0], bm[1]);
                mma_f16(o[2 * p + 1], a0, a1, a2, a3, bm[2], bm[3]);
            }
        }

        __syncthreads();   // KV + bias buffers fully consumed by all warps

        if (jt + 2 < NJT) {
            const int jn = (jt + 2) << 6;
            if (tid < 128)
                copy_kv(tid, jn, buf, b, h, qkv16, v16t, smc,
                        buf ? mb_kv1 : mb_kv0);
            else
                copy_bs(tid - 128, jn, buf, b, h, i0, bias16i, smc,
                        buf ? mb_bs1 : mb_bs0);
        }
    }

    // ---- epilogue: quad-reduce l, normalize + split-write O hi/lo ----
    l0 += __shfl_xor_sync(0xffffffffu, l0, 1);
    l0 += __shfl_xor_sync(0xffffffffu, l0, 2);
    l1 += __shfl_xor_sync(0xffffffffu, l1, 1);
    l1 += __shfl_xor_sync(0xffffffffu, l1, 2);
    const float inv0 = 1.0f / l0, inv1 = 1.0f / l1;
    const int row0 = i0 + rl0, row1 = i0 + rl1;
#pragma unroll
    for (int dd = 0; dd < 8; dd++) {
        const int col = h * DHH + dd * 8 + 2 * t;
        const float v00 = o[dd][0] * inv0, v01 = o[dd][1] * inv0;
        const float v10 = o[dd][2] * inv1, v11 = o[dd][3] * inv1;
        const __half2 h0 = __float22half2_rn(make_float2(v00, v01));
        const __half2 h1 = __float22half2_rn(make_float2(v10, v11));
        const float2 hf0 = __half22float2(h0);
        const float2 hf1 = __half22float2(h1);
        const __half2 q0 = __float22half2_rn(make_float2(v00 - hf0.x, v01 - hf0.y));
        const __half2 q1 = __float22half2_rn(make_float2(v10 - hf1.x, v11 - hf1.y));
        *(__half2*)(ohi + (size_t)(b * NT + row0) * INNER + col) = h0;
        *(__half2*)(ohi + (size_t)(b * NT + row1) * INNER + col) = h1;
        *(__half2*)(olo + (size_t)(b * NT + row0) * INNER + col) = q0;
        *(__half2*)(olo + (size_t)(b * NT + row1) * INNER + col) = q1;
    }
}

// ---------------------------------------------------------------------------
extern "C" void kernel_launch(void* const* d_in, const int* in_sizes, int n_in,
                              void* d_out, int out_size)
{
    const float* x     = (const float*)d_in[0];
    const float* cd    = (const float*)d_in[1];
    const float* Wqkv  = (const float*)d_in[2];
    const float* Wout  = (const float*)d_in[3];
    const float* bout  = (const float*)d_in[4];
    const float* rel_w = (const float*)d_in[5];
    const float* rel_b = (const float*)d_in[6];
    float* out = (float*)d_out;

    __half *xhi, *xlo, *wqh, *wql, *woh, *wol, *qkv16, *v16t, *ohi, *olo;
    short *bias16i;
    cudaGetSymbolAddress((void**)&xhi, g_xhi);
    cudaGetSymbolAddress((void**)&xlo, g_xlo);
    cudaGetSymbolAddress((void**)&wqh, g_wqh);
    cudaGetSymbolAddress((void**)&wql, g_wql);
    cudaGetSymbolAddress((void**)&woh, g_woh);
    cudaGetSymbolAddress((void**)&wol, g_wol);
    cudaGetSymbolAddress((void**)&qkv16, g_qkv16);
    cudaGetSymbolAddress((void**)&v16t, g_v16t);
    cudaGetSymbolAddress((void**)&bias16i, g_bias16i);
    cudaGetSymbolAddress((void**)&ohi, g_ohi);
    cudaGetSymbolAddress((void**)&olo, g_olo);

    cudaFuncSetAttribute(attn_kernel, cudaFuncAttributeMaxDynamicSharedMemorySize,
                         ATTN_SMEM_BYTES);
    cudaFuncSetAttribute(fused_pre_kernel,
                         cudaFuncAttributeMaxDynamicSharedMemorySize, 55296);
    cudaFuncSetAttribute(hgemm3_kernel<false>,
                         cudaFuncAttributeMaxDynamicSharedMemorySize, 55296);

    dim3 blk(256);
    // split x and weights to hi/lo fp16
    cvt_x_kernel<<<(BB * NT * DD) / (256 * 4), blk>>>(x, xhi, xlo);
    cvt_w_kernel<<<(QKVC * DD) / 256, blk>>>(Wqkv, wqh, wql, QKVC);
    cvt_w_kernel<<<(DD * DD) / 256, blk>>>(Wout, woh, wol, DD);
    // fused: int16 bias (conv1x1 * log2e, q10) blocks + qkv GEMM blocks
    fused_pre_kernel<<<FUSED_TOTAL, blk, 55296>>>(
        cd, rel_w, rel_b, bias16i, xhi, xlo, wqh, wql, qkv16);
    // v transpose per head
    vtrans_kernel<<<dim3(HH * (NT / 64), BB), blk>>>(qkv16, v16t);
    // fused attention -> split O
    attn_kernel<<<dim3(HH * (NT / 128), BB), blk, ATTN_SMEM_BYTES>>>(
        qkv16, v16t, bias16i, ohi, olo);
    // out = O @ Wout + bout  (split-fp16, fp32 out)
    hgemm3_kernel<false><<<dim3(DD / 64, (BB * NT) / 128), blk, 55296>>>(
        ohi, olo, woh, wol, bout, out, DD);
}